// round 14
// baseline (speedup 1.0000x reference)
#include <cuda_runtime.h>
#include <cuda_bf16.h>
#include <cstdint>

// ===========================================================================
// GATv2, 3 layers. N=20000, E=320000.
// Fused prep + hierarchical scan + split-bf16 mma GEMMs (R10 config, 3 CTA/SM)
// + CSR gather aggregation (2 nodes per block).
// ===========================================================================

#define N_MAX   20000
#define NPAD    20096            // 157 * 128
#define E_MAX   320000
#define SLOPE   0.2f
#define SCAN_B  512
#define SCAN_G  40

__device__ __align__(16) float g_FS[N_MAX * 256];
__device__ __align__(16) float g_FD[N_MAX * 256];
__device__ __align__(16) float g_HA[N_MAX * 256];
__device__ __align__(16) __nv_bfloat16 g_AH[NPAD * 256];
__device__ __align__(16) __nv_bfloat16 g_AL[NPAD * 256];
#define WT_TOTAL 311296
__device__ __align__(16) __nv_bfloat16 g_WH[WT_TOTAL];
__device__ __align__(16) __nv_bfloat16 g_WL[WT_TOTAL];
__device__ __align__(16) float g_BR2M[64];
__device__ int g_CNT[N_MAX];
__device__ int g_ROWPTR[N_MAX + 1];
__device__ int g_CURS[N_MAX];
__device__ int g_COL[E_MAX];
__device__ int g_BLKSUM[SCAN_G];

static inline int cdiv(int a, int b) { return (a + b - 1) / b; }

// ===========================================================================
// Fused prep: conv_x + wconv(+bm) + hist, one grid.
// items: [0, NX)             -> conv_x
//        [NX, NX+WT_TOTAL)   -> wconv
//        [.., .. + E)        -> hist
// ===========================================================================
struct PrepP {
    const float* x;
    const float* W[6]; const float* Wr2; const float* br2;
    const int* dst;
    __nv_bfloat16* AH; __nv_bfloat16* AL;
    __nv_bfloat16* WH; __nv_bfloat16* WL;
    float* bm;
    int* cnt;
    int NX; int E;
};

__global__ void prep_kernel(PrepP P) {
    int i = blockIdx.x * blockDim.x + threadIdx.x;
    if (i < 64) {
        float v = 0.f;
        if (i < 32) {
            #pragma unroll
            for (int h = 0; h < 6; h++) v += P.br2[h * 32 + i];
            v *= (1.f / 6.f);
        }
        P.bm[i] = v;
    }
    if (i < P.NX) {
        float v = P.x[i];
        __nv_bfloat16 h = __float2bfloat16(v);
        P.AH[i] = h;
        P.AL[i] = __float2bfloat16(v - __bfloat162float(h));
        return;
    }
    i -= P.NX;
    if (i < WT_TOTAL) {
        const int offs[8] = {0, 32768, 65536, 131072, 196608, 245760, 294912, 311296};
        const int Ks[7]   = {128, 128, 256, 256, 256, 256, 256};
        const int Ms[7]   = {256, 256, 256, 256, 192, 192, 64};
        int j = 0;
        #pragma unroll
        for (int q = 1; q < 7; q++) if (i >= offs[q]) j = q;
        int local = i - offs[j];
        int K = Ks[j];
        int n = local / K, k = local % K;
        float v;
        if (j < 6) {
            v = P.W[j][(size_t)k * Ms[j] + n];
        } else {
            v = 0.f;
            if (n < 32) {
                #pragma unroll
                for (int h = 0; h < 6; h++) v += P.Wr2[(size_t)k * 192 + h * 32 + n];
                v *= (1.f / 6.f);
            }
        }
        __nv_bfloat16 h = __float2bfloat16(v);
        P.WH[i] = h;
        P.WL[i] = __float2bfloat16(v - __bfloat162float(h));
        return;
    }
    i -= WT_TOTAL;
    if (i < P.E) atomicAdd(&P.cnt[P.dst[i]], 1);
}

// ===========================================================================
// Hierarchical scan (2 kernels) + fill
// ===========================================================================
__global__ __launch_bounds__(SCAN_B) void scan_blk_kernel(
    int* __restrict__ cnt, int* __restrict__ rowptr,
    int* __restrict__ blksum, int n)
{
    __shared__ int sm[SCAN_B];
    const int t = threadIdx.x;
    const int idx = blockIdx.x * SCAN_B + t;
    int v = (idx < n) ? cnt[idx] : 0;
    sm[t] = v;
    __syncthreads();
    for (int off = 1; off < SCAN_B; off <<= 1) {
        int u = (t >= off) ? sm[t - off] : 0;
        __syncthreads();
        sm[t] += u;
        __syncthreads();
    }
    if (idx < n) {
        rowptr[idx] = sm[t] - v;
        cnt[idx] = 0;
    }
    if (t == SCAN_B - 1) blksum[blockIdx.x] = sm[t];
}

__global__ __launch_bounds__(SCAN_B) void scan_fix_kernel(
    const int* __restrict__ blksum, int* __restrict__ rowptr,
    int* __restrict__ curs, int n)
{
    __shared__ int soff;
    const int b = blockIdx.x;
    const int t = threadIdx.x;
    if (t == 0) {
        int o = 0;
        for (int i = 0; i < b; i++) o += blksum[i];
        soff = o;
        if (b == gridDim.x - 1) rowptr[n] = o + blksum[b];
    }
    __syncthreads();
    const int off = soff;
    const int idx = b * SCAN_B + t;
    if (idx < n) {
        int r = rowptr[idx] + off;
        rowptr[idx] = r;
        curs[idx] = r;
    }
}

__global__ void fill_kernel(const int* __restrict__ src, const int* __restrict__ dst,
                            int* __restrict__ curs, int* __restrict__ col, int E) {
    int e = blockIdx.x * blockDim.x + threadIdx.x;
    if (e < E) {
        int pos = atomicAdd(&curs[dst[e]], 1);
        col[pos] = src[e];
    }
}

// ===========================================================================
// Split-bf16 mma GEMM (R10 config, 3 CTAs/SM).
// ===========================================================================
#define SPAD 40

struct MmaP {
    int   selMap[8];
    int   colMap[8];
    int   woff[3];
    const float* bias[3];
    float* C[3];
    int   Cld[3];
};

__device__ __forceinline__ void mma_bf16(float d[4], const uint32_t a[4],
                                         const uint32_t b[2]) {
    asm volatile(
        "mma.sync.aligned.m16n8k16.row.col.f32.bf16.bf16.f32 "
        "{%0,%1,%2,%3}, {%4,%5,%6,%7}, {%8,%9}, {%0,%1,%2,%3};"
        : "+f"(d[0]), "+f"(d[1]), "+f"(d[2]), "+f"(d[3])
        : "r"(a[0]), "r"(a[1]), "r"(a[2]), "r"(a[3]), "r"(b[0]), "r"(b[1]));
}

__device__ __forceinline__ void ldsm_x4(uint32_t r[4], const __nv_bfloat16* p) {
    uint32_t a = (uint32_t)__cvta_generic_to_shared(p);
    asm volatile("ldmatrix.sync.aligned.m8n8.x4.shared.b16 {%0,%1,%2,%3}, [%4];"
                 : "=r"(r[0]), "=r"(r[1]), "=r"(r[2]), "=r"(r[3]) : "r"(a));
}

__device__ __forceinline__ void cp16(void* smem, const void* g) {
    uint32_t s = (uint32_t)__cvta_generic_to_shared(smem);
    asm volatile("cp.async.cg.shared.global [%0], [%1], 16;" :: "r"(s), "l"(g));
}
#define CP_COMMIT() asm volatile("cp.async.commit_group;" ::: "memory")

__global__ __launch_bounds__(256, 3) void gemm_mma_kernel(
    const __nv_bfloat16* __restrict__ AH, const __nv_bfloat16* __restrict__ AL,
    const __nv_bfloat16* __restrict__ WHg, const __nv_bfloat16* __restrict__ WLg,
    MmaP P, int Nrows, int K)
{
    __shared__ __align__(16) __nv_bfloat16 sA[2][2][128][SPAD];
    __shared__ __align__(16) __nv_bfloat16 sB[2][2][64][SPAD];

    const int tid  = threadIdx.x;
    const int wid  = tid >> 5;
    const int lane = tid & 31;
    const int wm   = wid & 3;
    const int wn   = wid >> 2;

    const int sel     = P.selMap[blockIdx.y];
    const int colBase = P.colMap[blockIdx.y];
    const int rowBase = blockIdx.x * 128;

    const __nv_bfloat16* __restrict__ WH = WHg + P.woff[sel];
    const __nv_bfloat16* __restrict__ WL = WLg + P.woff[sel];

    float acc[2][4][4];
    #pragma unroll
    for (int i = 0; i < 2; i++)
        #pragma unroll
        for (int j = 0; j < 4; j++)
            #pragma unroll
            for (int q = 0; q < 4; q++) acc[i][j][q] = 0.f;

    const int aRow = (lane & 15);
    const int aColOff = ((lane >> 4) << 3);
    const int bRow = (lane & 7) | ((lane & 16) >> 1);
    const int bColOff = (lane & 8);

    const int nStages = K / 32;

    auto fill = [&](int s, int buf) {
        const int kB = s * 32;
        #pragma unroll
        for (int i = 0; i < 2; i++) {
            int j = tid * 2 + i;
            int r = j >> 2, sl = j & 3;
            cp16(&sA[buf][0][r][sl * 8], &AH[(size_t)(rowBase + r) * K + kB + sl * 8]);
            cp16(&sA[buf][1][r][sl * 8], &AL[(size_t)(rowBase + r) * K + kB + sl * 8]);
        }
        {
            int r = tid >> 2, sl = tid & 3;
            cp16(&sB[buf][0][r][sl * 8], &WH[(size_t)(colBase + r) * K + kB + sl * 8]);
            cp16(&sB[buf][1][r][sl * 8], &WL[(size_t)(colBase + r) * K + kB + sl * 8]);
        }
        CP_COMMIT();
    };

    fill(0, 0);

    for (int s = 0; s < nStages; s++) {
        const int buf = s & 1;
        if (s + 1 < nStages) {
            fill(s + 1, buf ^ 1);
            asm volatile("cp.async.wait_group 1;" ::: "memory");
        } else {
            asm volatile("cp.async.wait_group 0;" ::: "memory");
        }
        __syncthreads();

        #pragma unroll
        for (int ks = 0; ks < 32; ks += 16) {
            uint32_t ah[2][4], al[2][4];
            #pragma unroll
            for (int mt = 0; mt < 2; mt++) {
                const int r = wm * 32 + mt * 16 + aRow;
                const int c = ks + aColOff;
                ldsm_x4(ah[mt], &sA[buf][0][r][c]);
                ldsm_x4(al[mt], &sA[buf][1][r][c]);
            }
            uint32_t bh[4][2], bl[4][2];
            #pragma unroll
            for (int np = 0; np < 2; np++) {
                const int n0 = wn * 32 + np * 16 + bRow;
                const int c = ks + bColOff;
                uint32_t t[4];
                ldsm_x4(t, &sB[buf][0][n0][c]);
                bh[np * 2][0] = t[0];     bh[np * 2][1] = t[1];
                bh[np * 2 + 1][0] = t[2]; bh[np * 2 + 1][1] = t[3];
                ldsm_x4(t, &sB[buf][1][n0][c]);
                bl[np * 2][0] = t[0];     bl[np * 2][1] = t[1];
                bl[np * 2 + 1][0] = t[2]; bl[np * 2 + 1][1] = t[3];
            }
            #pragma unroll
            for (int mt = 0; mt < 2; mt++)
                #pragma unroll
                for (int nt = 0; nt < 4; nt++) {
                    mma_bf16(acc[mt][nt], ah[mt], bh[nt]);
                    mma_bf16(acc[mt][nt], al[mt], bh[nt]);
                    mma_bf16(acc[mt][nt], ah[mt], bl[nt]);
                }
        }
        __syncthreads();
    }

    const int g  = lane >> 2;
    const int t4 = lane & 3;
    float* C = P.C[sel];
    const int Cld = P.Cld[sel];
    const float* bias = P.bias[sel];
    #pragma unroll
    for (int mt = 0; mt < 2; mt++) {
        const int r0 = rowBase + wm * 32 + mt * 16 + g;
        #pragma unroll
        for (int nt = 0; nt < 4; nt++) {
            const int cc = colBase + wn * 32 + nt * 8 + 2 * t4;
            const float b0 = __ldg(&bias[cc]);
            const float b1 = __ldg(&bias[cc + 1]);
            if (r0 < Nrows) {
                float2 v = make_float2(acc[mt][nt][0] + b0, acc[mt][nt][1] + b1);
                *reinterpret_cast<float2*>(&C[(size_t)r0 * Cld + cc]) = v;
            }
            if (r0 + 8 < Nrows) {
                float2 v = make_float2(acc[mt][nt][2] + b0, acc[mt][nt][3] + b1);
                *reinterpret_cast<float2*>(&C[(size_t)(r0 + 8) * Cld + cc]) = v;
            }
        }
    }
}

// ===========================================================================
// Aggregation, layers 0/1 (H=4, D=64): 2 nodes per block (8 warps).
// warp w: node = blockIdx*2 + (w>>2), head = w&3. Unroll 4.
// ===========================================================================
template <int RES, int WRITE_F32>
__global__ __launch_bounds__(256) void gat_agg_h4d64_kernel(
    const int* __restrict__ rowptr, const int* __restrict__ col,
    const float* __restrict__ FS, const float* __restrict__ FD,
    const float* __restrict__ attn,
    const float* __restrict__ resid, float* __restrict__ out,
    __nv_bfloat16* __restrict__ AH, __nv_bfloat16* __restrict__ AL,
    int N)
{
    const int wfull = threadIdx.x >> 5;
    const int node  = blockIdx.x * 2 + (wfull >> 2);
    const int w     = wfull & 3;
    const int lane  = threadIdx.x & 31;
    if (node >= N) return;

    const int off = w * 64 + lane;
    const float fd0 = FD[(size_t)node * 256 + off];
    const float fd1 = FD[(size_t)node * 256 + off + 32];
    const float at0 = __ldg(&attn[w * 64 + lane]);
    const float at1 = __ldg(&attn[w * 64 + lane + 32]);

    float s0 = 0.f, s1 = 0.f, den = 0.f;

    int p = rowptr[node];
    const int pEnd = rowptr[node + 1];

    for (; p + 4 <= pEnd; p += 4) {
        int sn0 = col[p], sn1 = col[p + 1], sn2 = col[p + 2], sn3 = col[p + 3];
        float f00 = FS[(size_t)sn0 * 256 + off], f01 = FS[(size_t)sn0 * 256 + off + 32];
        float f10 = FS[(size_t)sn1 * 256 + off], f11 = FS[(size_t)sn1 * 256 + off + 32];
        float f20 = FS[(size_t)sn2 * 256 + off], f21 = FS[(size_t)sn2 * 256 + off + 32];
        float f30 = FS[(size_t)sn3 * 256 + off], f31 = FS[(size_t)sn3 * 256 + off + 32];

        float v, t0, t1, t2, t3;
        v = f00 + fd0; v = (v > 0.f) ? v : SLOPE * v; t0  = v * at0;
        v = f01 + fd1; v = (v > 0.f) ? v : SLOPE * v; t0 += v * at1;
        v = f10 + fd0; v = (v > 0.f) ? v : SLOPE * v; t1  = v * at0;
        v = f11 + fd1; v = (v > 0.f) ? v : SLOPE * v; t1 += v * at1;
        v = f20 + fd0; v = (v > 0.f) ? v : SLOPE * v; t2  = v * at0;
        v = f21 + fd1; v = (v > 0.f) ? v : SLOPE * v; t2 += v * at1;
        v = f30 + fd0; v = (v > 0.f) ? v : SLOPE * v; t3  = v * at0;
        v = f31 + fd1; v = (v > 0.f) ? v : SLOPE * v; t3 += v * at1;

        #pragma unroll
        for (int o = 16; o > 0; o >>= 1) {
            t0 += __shfl_xor_sync(0xffffffffu, t0, o);
            t1 += __shfl_xor_sync(0xffffffffu, t1, o);
            t2 += __shfl_xor_sync(0xffffffffu, t2, o);
            t3 += __shfl_xor_sync(0xffffffffu, t3, o);
        }
        float e0 = __expf(t0), e1 = __expf(t1), e2 = __expf(t2), e3 = __expf(t3);
        den += (e0 + e1) + (e2 + e3);
        s0 += f00 * e0 + f10 * e1 + f20 * e2 + f30 * e3;
        s1 += f01 * e0 + f11 * e1 + f21 * e2 + f31 * e3;
    }
    for (; p < pEnd; p++) {
        int sn = col[p];
        float f0 = FS[(size_t)sn * 256 + off];
        float f1 = FS[(size_t)sn * 256 + off + 32];
        float v0 = f0 + fd0; v0 = (v0 > 0.f) ? v0 : SLOPE * v0;
        float v1 = f1 + fd1; v1 = (v1 > 0.f) ? v1 : SLOPE * v1;
        float t = v0 * at0 + v1 * at1;
        #pragma unroll
        for (int o = 16; o > 0; o >>= 1) t += __shfl_xor_sync(0xffffffffu, t, o);
        float ex = __expf(t);
        den += ex; s0 += f0 * ex; s1 += f1 * ex;
    }

    const float inv = (den > 0.f) ? (1.f / den) : 0.f;
    float o0 = s0 * inv;
    float o1 = s1 * inv;
    if (RES) {
        o0 += resid[(size_t)node * 256 + off];
        o1 += resid[(size_t)node * 256 + off + 32];
    }
    o0 = (o0 > 0.f) ? o0 : expm1f(o0);
    o1 = (o1 > 0.f) ? o1 : expm1f(o1);
    if (WRITE_F32) {
        out[(size_t)node * 256 + off]      = o0;
        out[(size_t)node * 256 + off + 32] = o1;
    }
    __nv_bfloat16 h0 = __float2bfloat16(o0);
    __nv_bfloat16 h1 = __float2bfloat16(o1);
    AH[(size_t)node * 256 + off]      = h0;
    AH[(size_t)node * 256 + off + 32] = h1;
    AL[(size_t)node * 256 + off]      = __float2bfloat16(o0 - __bfloat162float(h0));
    AL[(size_t)node * 256 + off + 32] = __float2bfloat16(o1 - __bfloat162float(h1));
}

// ===========================================================================
// Aggregation, layer 2 (H=6, D=32): 2 nodes per block (12 warps).
// ===========================================================================
__global__ __launch_bounds__(384) void gat_agg_l2_kernel(
    const int* __restrict__ rowptr, const int* __restrict__ col,
    const float* __restrict__ FS, const float* __restrict__ FD,
    const float* __restrict__ attn,
    const float* __restrict__ resm, float* __restrict__ out, int N)
{
    __shared__ float sm[2][192];
    const int wfull = threadIdx.x >> 5;
    const int half  = wfull / 6;           // 0 or 1
    const int node  = blockIdx.x * 2 + half;
    const int w     = wfull % 6;
    const int lane  = threadIdx.x & 31;

    if (node < N) {
        const int off = w * 32 + lane;
        const float fd = FD[(size_t)node * 192 + off];
        const float at = __ldg(&attn[off]);

        float s = 0.f, den = 0.f;

        int p = rowptr[node];
        const int pEnd = rowptr[node + 1];

        for (; p + 4 <= pEnd; p += 4) {
            int sn0 = col[p], sn1 = col[p + 1], sn2 = col[p + 2], sn3 = col[p + 3];
            float f0 = FS[(size_t)sn0 * 192 + off];
            float f1 = FS[(size_t)sn1 * 192 + off];
            float f2 = FS[(size_t)sn2 * 192 + off];
            float f3 = FS[(size_t)sn3 * 192 + off];
            float v, t0, t1, t2, t3;
            v = f0 + fd; v = (v > 0.f) ? v : SLOPE * v; t0 = v * at;
            v = f1 + fd; v = (v > 0.f) ? v : SLOPE * v; t1 = v * at;
            v = f2 + fd; v = (v > 0.f) ? v : SLOPE * v; t2 = v * at;
            v = f3 + fd; v = (v > 0.f) ? v : SLOPE * v; t3 = v * at;
            #pragma unroll
            for (int o = 16; o > 0; o >>= 1) {
                t0 += __shfl_xor_sync(0xffffffffu, t0, o);
                t1 += __shfl_xor_sync(0xffffffffu, t1, o);
                t2 += __shfl_xor_sync(0xffffffffu, t2, o);
                t3 += __shfl_xor_sync(0xffffffffu, t3, o);
            }
            float e0 = __expf(t0), e1 = __expf(t1), e2 = __expf(t2), e3 = __expf(t3);
            den += (e0 + e1) + (e2 + e3);
            s += f0 * e0 + f1 * e1 + f2 * e2 + f3 * e3;
        }
        for (; p < pEnd; p++) {
            int sn = col[p];
            float f = FS[(size_t)sn * 192 + off];
            float v = f + fd; v = (v > 0.f) ? v : SLOPE * v;
            float t = v * at;
            #pragma unroll
            for (int o = 16; o > 0; o >>= 1) t += __shfl_xor_sync(0xffffffffu, t, o);
            float ex = __expf(t);
            den += ex; s += f * ex;
        }

        const float inv = (den > 0.f) ? (1.f / den) : 0.f;
        sm[half][off] = s * inv;
    }
    __syncthreads();

    if (node < N && w == 0) {
        float m = 0.f;
        #pragma unroll
        for (int h = 0; h < 6; h++) m += sm[half][h * 32 + lane];
        out[(size_t)node * 32 + lane] = m * (1.f / 6.f) + resm[(size_t)node * 64 + lane];
    }
}

// ===========================================================================
// Host driver
// ===========================================================================
extern "C" void kernel_launch(void* const* d_in, const int* in_sizes, int n_in,
                              void* d_out, int out_size)
{
    const float* x   = (const float*)d_in[0];
    const int*   src = (const int*)d_in[1];
    const int*   dst = (const int*)d_in[2];
    const float* W0s = (const float*)d_in[3];
    const float* b0s = (const float*)d_in[4];
    const float* W0d = (const float*)d_in[5];
    const float* b0d = (const float*)d_in[6];
    const float* a0  = (const float*)d_in[7];
    const float* W1s = (const float*)d_in[8];
    const float* b1s = (const float*)d_in[9];
    const float* W1d = (const float*)d_in[10];
    const float* b1d = (const float*)d_in[11];
    const float* a1  = (const float*)d_in[12];
    const float* W2s = (const float*)d_in[13];
    const float* b2s = (const float*)d_in[14];
    const float* W2d = (const float*)d_in[15];
    const float* b2d = (const float*)d_in[16];
    const float* a2  = (const float*)d_in[17];
    const float* Wr2 = (const float*)d_in[18];
    const float* br2 = (const float*)d_in[19];

    const int N = in_sizes[0] / 128;
    const int E = in_sizes[1];

    float *FS, *FD, *HA, *BR2M;
    __nv_bfloat16 *AH, *AL, *WH, *WL;
    int *CNT, *ROWPTR, *CURS, *COL, *BLKSUM;
    cudaGetSymbolAddress((void**)&FS, g_FS);
    cudaGetSymbolAddress((void**)&FD, g_FD);
    cudaGetSymbolAddress((void**)&HA, g_HA);
    cudaGetSymbolAddress((void**)&BR2M, g_BR2M);
    cudaGetSymbolAddress((void**)&AH, g_AH);
    cudaGetSymbolAddress((void**)&AL, g_AL);
    cudaGetSymbolAddress((void**)&WH, g_WH);
    cudaGetSymbolAddress((void**)&WL, g_WL);
    cudaGetSymbolAddress((void**)&CNT, g_CNT);
    cudaGetSymbolAddress((void**)&ROWPTR, g_ROWPTR);
    cudaGetSymbolAddress((void**)&CURS, g_CURS);
    cudaGetSymbolAddress((void**)&COL, g_COL);
    cudaGetSymbolAddress((void**)&BLKSUM, g_BLKSUM);

    float* out = (float*)d_out;

    const int TB = 256;
    const int mTiles = cdiv(N, 128);

    // order: prep(1) scan_blk(2) scan_fix(3) gemm0(4=profiled) fill(5) agg0(6)...
    {
        PrepP pp;
        pp.x = x;
        pp.W[0] = W0s; pp.W[1] = W0d; pp.W[2] = W1s; pp.W[3] = W1d;
        pp.W[4] = W2s; pp.W[5] = W2d; pp.Wr2 = Wr2; pp.br2 = br2;
        pp.dst = dst;
        pp.AH = AH; pp.AL = AL; pp.WH = WH; pp.WL = WL;
        pp.bm = BR2M; pp.cnt = CNT;
        pp.NX = N * 128; pp.E = E;
        const int total = pp.NX + WT_TOTAL + E;
        prep_kernel<<<cdiv(total, TB), TB>>>(pp);
    }
    scan_blk_kernel<<<SCAN_G, SCAN_B>>>(CNT, ROWPTR, BLKSUM, N);
    scan_fix_kernel<<<SCAN_G, SCAN_B>>>(BLKSUM, ROWPTR, CURS, N);

    // ---------------- Layer 0 GEMM: K=128 -> FS, FD ----------------
    {
        MmaP P;
        for (int i = 0; i < 8; i++) { P.selMap[i] = i >> 2; P.colMap[i] = (i & 3) * 64; }
        P.woff[0] = 0;     P.bias[0] = b0s; P.C[0] = FS; P.Cld[0] = 256;
        P.woff[1] = 32768; P.bias[1] = b0d; P.C[1] = FD; P.Cld[1] = 256;
        P.woff[2] = 0;     P.bias[2] = b0s; P.C[2] = FS; P.Cld[2] = 256;
        dim3 grid(mTiles, 8);
        gemm_mma_kernel<<<grid, 256>>>(AH, AL, WH, WL, P, N, 128);
    }

    fill_kernel<<<cdiv(E, TB), TB>>>(src, dst, CURS, COL, E);

    gat_agg_h4d64_kernel<0, 1><<<cdiv(N, 2), 256>>>(ROWPTR, COL, FS, FD, a0, nullptr, HA, AH, AL, N);

    // ---------------- Layer 1: K=256 -> FS, FD ----------------
    {
        MmaP P;
        for (int i = 0; i < 8; i++) { P.selMap[i] = i >> 2; P.colMap[i] = (i & 3) * 64; }
        P.woff[0] = 65536;  P.bias[0] = b1s; P.C[0] = FS; P.Cld[0] = 256;
        P.woff[1] = 131072; P.bias[1] = b1d; P.C[1] = FD; P.Cld[1] = 256;
        P.woff[2] = 0;      P.bias[2] = b1s; P.C[2] = FS; P.Cld[2] = 256;
        dim3 grid(mTiles, 8);
        gemm_mma_kernel<<<grid, 256>>>(AH, AL, WH, WL, P, N, 256);
    }
    gat_agg_h4d64_kernel<1, 0><<<cdiv(N, 2), 256>>>(ROWPTR, COL, FS, FD, a1, HA, nullptr, AH, AL, N);

    // ---------------- Layer 2: K=256 -> FS, FD (192) + resm (64) ------
    {
        MmaP P;
        const int sm_[7] = {0, 0, 0, 1, 1, 1, 2};
        const int cm_[7] = {0, 64, 128, 0, 64, 128, 0};
        for (int i = 0; i < 7; i++) { P.selMap[i] = sm_[i]; P.colMap[i] = cm_[i]; }
        P.selMap[7] = 0; P.colMap[7] = 0;
        P.woff[0] = 196608; P.bias[0] = b2s;  P.C[0] = FS; P.Cld[0] = 192;
        P.woff[1] = 245760; P.bias[1] = b2d;  P.C[1] = FD; P.Cld[1] = 192;
        P.woff[2] = 294912; P.bias[2] = BR2M; P.C[2] = HA; P.Cld[2] = 64;
        dim3 grid(mTiles, 7);
        gemm_mma_kernel<<<grid, 256>>>(AH, AL, WH, WL, P, N, 256);
    }
    gat_agg_l2_kernel<<<cdiv(N, 2), 384>>>(ROWPTR, COL, FS, FD, a2, HA, out, N);
}

// round 15
// speedup vs baseline: 1.0836x; 1.0836x over previous
#include <cuda_runtime.h>
#include <cuda_bf16.h>
#include <cstdint>

// ===========================================================================
// GATv2, 3 layers. N=20000, E=320000.
// R13 baseline + packed multi-reduce in aggregation kernels.
// ===========================================================================

#define N_MAX   20000
#define NPAD    20096
#define E_MAX   320000
#define SLOPE   0.2f
#define SCAN_B  512
#define SCAN_G  40

__device__ __align__(16) float g_FS[N_MAX * 256];
__device__ __align__(16) float g_FD[N_MAX * 256];
__device__ __align__(16) float g_HA[N_MAX * 256];
__device__ __align__(16) __nv_bfloat16 g_AH[NPAD * 256];
__device__ __align__(16) __nv_bfloat16 g_AL[NPAD * 256];
#define WT_TOTAL 311296
__device__ __align__(16) __nv_bfloat16 g_WH[WT_TOTAL];
__device__ __align__(16) __nv_bfloat16 g_WL[WT_TOTAL];
__device__ __align__(16) float g_BR2M[64];
__device__ int g_CNT[N_MAX];
__device__ int g_ROWPTR[N_MAX + 1];
__device__ int g_CURS[N_MAX];
__device__ int g_COL[E_MAX];
__device__ int g_BLKSUM[SCAN_G];

static inline int cdiv(int a, int b) { return (a + b - 1) / b; }

// ===========================================================================
// CSR build
// ===========================================================================
__global__ void hist_kernel(const int* __restrict__ dst, int* __restrict__ cnt, int E) {
    int e = blockIdx.x * blockDim.x + threadIdx.x;
    if (e < E) atomicAdd(&cnt[dst[e]], 1);
}

__global__ __launch_bounds__(SCAN_B) void scan_blk_kernel(
    int* __restrict__ cnt, int* __restrict__ rowptr,
    int* __restrict__ blksum, int n)
{
    __shared__ int sm[SCAN_B];
    const int t = threadIdx.x;
    const int idx = blockIdx.x * SCAN_B + t;
    int v = (idx < n) ? cnt[idx] : 0;
    sm[t] = v;
    __syncthreads();
    for (int off = 1; off < SCAN_B; off <<= 1) {
        int u = (t >= off) ? sm[t - off] : 0;
        __syncthreads();
        sm[t] += u;
        __syncthreads();
    }
    if (idx < n) {
        rowptr[idx] = sm[t] - v;
        cnt[idx] = 0;
    }
    if (t == SCAN_B - 1) blksum[blockIdx.x] = sm[t];
}

__global__ __launch_bounds__(SCAN_B) void scan_fix_kernel(
    const int* __restrict__ blksum, int* __restrict__ rowptr,
    int* __restrict__ curs, int n)
{
    __shared__ int soff;
    const int b = blockIdx.x;
    const int t = threadIdx.x;
    if (t == 0) {
        int o = 0;
        for (int i = 0; i < b; i++) o += blksum[i];
        soff = o;
        if (b == gridDim.x - 1) rowptr[n] = o + blksum[b];
    }
    __syncthreads();
    const int off = soff;
    const int idx = b * SCAN_B + t;
    if (idx < n) {
        int r = rowptr[idx] + off;
        rowptr[idx] = r;
        curs[idx] = r;
    }
}

__global__ void fill_kernel(const int* __restrict__ src, const int* __restrict__ dst,
                            int* __restrict__ curs, int* __restrict__ col, int E) {
    int e = blockIdx.x * blockDim.x + threadIdx.x;
    if (e < E) {
        int pos = atomicAdd(&curs[dst[e]], 1);
        col[pos] = src[e];
    }
}

// ===========================================================================
// Weight conversion
// ===========================================================================
struct WcP { const float* W[6]; const float* Wr2; const float* br2; };

__global__ void wconv_kernel(WcP P, __nv_bfloat16* __restrict__ WH,
                             __nv_bfloat16* __restrict__ WL, float* __restrict__ bm) {
    int i = blockIdx.x * blockDim.x + threadIdx.x;
    if (i < 64) {
        float v = 0.f;
        if (i < 32) {
            #pragma unroll
            for (int h = 0; h < 6; h++) v += P.br2[h * 32 + i];
            v *= (1.f / 6.f);
        }
        bm[i] = v;
    }
    if (i >= WT_TOTAL) return;
    const int offs[8] = {0, 32768, 65536, 131072, 196608, 245760, 294912, 311296};
    const int Ks[7]   = {128, 128, 256, 256, 256, 256, 256};
    const int Ms[7]   = {256, 256, 256, 256, 192, 192, 64};
    int j = 0;
    #pragma unroll
    for (int q = 1; q < 7; q++) if (i >= offs[q]) j = q;
    int local = i - offs[j];
    int K = Ks[j];
    int n = local / K, k = local % K;
    float v;
    if (j < 6) {
        v = P.W[j][(size_t)k * Ms[j] + n];
    } else {
        v = 0.f;
        if (n < 32) {
            #pragma unroll
            for (int h = 0; h < 6; h++) v += P.Wr2[(size_t)k * 192 + h * 32 + n];
            v *= (1.f / 6.f);
        }
    }
    __nv_bfloat16 h = __float2bfloat16(v);
    WH[i] = h;
    WL[i] = __float2bfloat16(v - __bfloat162float(h));
}

__global__ void conv_x_kernel(const float* __restrict__ x,
                              __nv_bfloat16* __restrict__ AH,
                              __nv_bfloat16* __restrict__ AL, int n) {
    int i = blockIdx.x * blockDim.x + threadIdx.x;
    if (i >= n) return;
    float v = x[i];
    __nv_bfloat16 h = __float2bfloat16(v);
    AH[i] = h;
    AL[i] = __float2bfloat16(v - __bfloat162float(h));
}

// ===========================================================================
// Split-bf16 mma GEMM (R10 config).
// ===========================================================================
#define SPAD 40

struct MmaP {
    int   selMap[8];
    int   colMap[8];
    int   woff[3];
    const float* bias[3];
    float* C[3];
    int   Cld[3];
};

__device__ __forceinline__ void mma_bf16(float d[4], const uint32_t a[4],
                                         const uint32_t b[2]) {
    asm volatile(
        "mma.sync.aligned.m16n8k16.row.col.f32.bf16.bf16.f32 "
        "{%0,%1,%2,%3}, {%4,%5,%6,%7}, {%8,%9}, {%0,%1,%2,%3};"
        : "+f"(d[0]), "+f"(d[1]), "+f"(d[2]), "+f"(d[3])
        : "r"(a[0]), "r"(a[1]), "r"(a[2]), "r"(a[3]), "r"(b[0]), "r"(b[1]));
}

__device__ __forceinline__ void ldsm_x4(uint32_t r[4], const __nv_bfloat16* p) {
    uint32_t a = (uint32_t)__cvta_generic_to_shared(p);
    asm volatile("ldmatrix.sync.aligned.m8n8.x4.shared.b16 {%0,%1,%2,%3}, [%4];"
                 : "=r"(r[0]), "=r"(r[1]), "=r"(r[2]), "=r"(r[3]) : "r"(a));
}

__device__ __forceinline__ void cp16(void* smem, const void* g) {
    uint32_t s = (uint32_t)__cvta_generic_to_shared(smem);
    asm volatile("cp.async.cg.shared.global [%0], [%1], 16;" :: "r"(s), "l"(g));
}
#define CP_COMMIT() asm volatile("cp.async.commit_group;" ::: "memory")

__global__ __launch_bounds__(256) void gemm_mma_kernel(
    const __nv_bfloat16* __restrict__ AH, const __nv_bfloat16* __restrict__ AL,
    const __nv_bfloat16* __restrict__ WHg, const __nv_bfloat16* __restrict__ WLg,
    MmaP P, int Nrows, int K)
{
    __shared__ __align__(16) __nv_bfloat16 sA[2][2][128][SPAD];
    __shared__ __align__(16) __nv_bfloat16 sB[2][2][64][SPAD];

    const int tid  = threadIdx.x;
    const int wid  = tid >> 5;
    const int lane = tid & 31;
    const int wm   = wid & 3;
    const int wn   = wid >> 2;

    const int sel     = P.selMap[blockIdx.y];
    const int colBase = P.colMap[blockIdx.y];
    const int rowBase = blockIdx.x * 128;

    const __nv_bfloat16* __restrict__ WH = WHg + P.woff[sel];
    const __nv_bfloat16* __restrict__ WL = WLg + P.woff[sel];

    float acc[2][4][4];
    #pragma unroll
    for (int i = 0; i < 2; i++)
        #pragma unroll
        for (int j = 0; j < 4; j++)
            #pragma unroll
            for (int q = 0; q < 4; q++) acc[i][j][q] = 0.f;

    const int aRow = (lane & 15);
    const int aColOff = ((lane >> 4) << 3);
    const int bRow = (lane & 7) | ((lane & 16) >> 1);
    const int bColOff = (lane & 8);

    const int nStages = K / 32;

    auto fill = [&](int s, int buf) {
        const int kB = s * 32;
        #pragma unroll
        for (int i = 0; i < 2; i++) {
            int j = tid * 2 + i;
            int r = j >> 2, sl = j & 3;
            cp16(&sA[buf][0][r][sl * 8], &AH[(size_t)(rowBase + r) * K + kB + sl * 8]);
            cp16(&sA[buf][1][r][sl * 8], &AL[(size_t)(rowBase + r) * K + kB + sl * 8]);
        }
        {
            int r = tid >> 2, sl = tid & 3;
            cp16(&sB[buf][0][r][sl * 8], &WH[(size_t)(colBase + r) * K + kB + sl * 8]);
            cp16(&sB[buf][1][r][sl * 8], &WL[(size_t)(colBase + r) * K + kB + sl * 8]);
        }
        CP_COMMIT();
    };

    fill(0, 0);

    for (int s = 0; s < nStages; s++) {
        const int buf = s & 1;
        if (s + 1 < nStages) {
            fill(s + 1, buf ^ 1);
            asm volatile("cp.async.wait_group 1;" ::: "memory");
        } else {
            asm volatile("cp.async.wait_group 0;" ::: "memory");
        }
        __syncthreads();

        #pragma unroll
        for (int ks = 0; ks < 32; ks += 16) {
            uint32_t ah[2][4], al[2][4];
            #pragma unroll
            for (int mt = 0; mt < 2; mt++) {
                const int r = wm * 32 + mt * 16 + aRow;
                const int c = ks + aColOff;
                ldsm_x4(ah[mt], &sA[buf][0][r][c]);
                ldsm_x4(al[mt], &sA[buf][1][r][c]);
            }
            uint32_t bh[4][2], bl[4][2];
            #pragma unroll
            for (int np = 0; np < 2; np++) {
                const int n0 = wn * 32 + np * 16 + bRow;
                const int c = ks + bColOff;
                uint32_t t[4];
                ldsm_x4(t, &sB[buf][0][n0][c]);
                bh[np * 2][0] = t[0];     bh[np * 2][1] = t[1];
                bh[np * 2 + 1][0] = t[2]; bh[np * 2 + 1][1] = t[3];
                ldsm_x4(t, &sB[buf][1][n0][c]);
                bl[np * 2][0] = t[0];     bl[np * 2][1] = t[1];
                bl[np * 2 + 1][0] = t[2]; bl[np * 2 + 1][1] = t[3];
            }
            #pragma unroll
            for (int mt = 0; mt < 2; mt++)
                #pragma unroll
                for (int nt = 0; nt < 4; nt++) {
                    mma_bf16(acc[mt][nt], ah[mt], bh[nt]);
                    mma_bf16(acc[mt][nt], al[mt], bh[nt]);
                    mma_bf16(acc[mt][nt], ah[mt], bl[nt]);
                }
        }
        __syncthreads();
    }

    const int g  = lane >> 2;
    const int t4 = lane & 3;
    float* C = P.C[sel];
    const int Cld = P.Cld[sel];
    const float* bias = P.bias[sel];
    #pragma unroll
    for (int mt = 0; mt < 2; mt++) {
        const int r0 = rowBase + wm * 32 + mt * 16 + g;
        #pragma unroll
        for (int nt = 0; nt < 4; nt++) {
            const int cc = colBase + wn * 32 + nt * 8 + 2 * t4;
            const float b0 = __ldg(&bias[cc]);
            const float b1 = __ldg(&bias[cc + 1]);
            if (r0 < Nrows) {
                float2 v = make_float2(acc[mt][nt][0] + b0, acc[mt][nt][1] + b1);
                *reinterpret_cast<float2*>(&C[(size_t)r0 * Cld + cc]) = v;
            }
            if (r0 + 8 < Nrows) {
                float2 v = make_float2(acc[mt][nt][2] + b0, acc[mt][nt][3] + b1);
                *reinterpret_cast<float2*>(&C[(size_t)(r0 + 8) * Cld + cc]) = v;
            }
        }
    }
}

// ===========================================================================
// Packed 4-way warp reduce: input t0..t3 (per-lane partials of 4 sums);
// output e0..e3 = expf(full sums), broadcast to all lanes. 13 shfl + 1 expf.
// ===========================================================================
__device__ __forceinline__ void multi_reduce_exp4(
    float t0, float t1, float t2, float t3,
    float& e0, float& e1, float& e2, float& e3)
{
    const unsigned m = 0xffffffffu;
    const int lane = threadIdx.x & 31;
    float r0 = t0 + __shfl_xor_sync(m, t0, 1);
    float r1 = t1 + __shfl_xor_sync(m, t1, 1);
    float r2 = t2 + __shfl_xor_sync(m, t2, 1);
    float r3 = t3 + __shfl_xor_sync(m, t3, 1);
    float p = (lane & 1) ? r1 : r0;
    float q = (lane & 1) ? r3 : r2;
    p += __shfl_xor_sync(m, p, 2);
    q += __shfl_xor_sync(m, q, 2);
    float u = (lane & 2) ? q : p;
    u += __shfl_xor_sync(m, u, 4);
    u += __shfl_xor_sync(m, u, 8);
    u += __shfl_xor_sync(m, u, 16);
    // lane l holds full sum of edge (l & 3)
    float ex = __expf(u);
    e0 = __shfl_sync(m, ex, 0);
    e1 = __shfl_sync(m, ex, 1);
    e2 = __shfl_sync(m, ex, 2);
    e3 = __shfl_sync(m, ex, 3);
}

// ===========================================================================
// Aggregation, layers 0/1 (H=4, D=64), unroll 4 with packed reduce.
// ===========================================================================
template <int RES, int WRITE_F32>
__global__ __launch_bounds__(128) void gat_agg_h4d64_kernel(
    const int* __restrict__ rowptr, const int* __restrict__ col,
    const float* __restrict__ FS, const float* __restrict__ FD,
    const float* __restrict__ attn,
    const float* __restrict__ resid, float* __restrict__ out,
    __nv_bfloat16* __restrict__ AH, __nv_bfloat16* __restrict__ AL)
{
    const int node = blockIdx.x;
    const int w = threadIdx.x >> 5;
    const int lane = threadIdx.x & 31;

    const int off = w * 64 + lane;
    const float fd0 = FD[(size_t)node * 256 + off];
    const float fd1 = FD[(size_t)node * 256 + off + 32];
    const float at0 = __ldg(&attn[w * 64 + lane]);
    const float at1 = __ldg(&attn[w * 64 + lane + 32]);

    float s0 = 0.f, s1 = 0.f, den = 0.f;

    int p = rowptr[node];
    const int pEnd = rowptr[node + 1];

    for (; p + 4 <= pEnd; p += 4) {
        int sn0 = col[p], sn1 = col[p + 1], sn2 = col[p + 2], sn3 = col[p + 3];
        float f00 = FS[(size_t)sn0 * 256 + off], f01 = FS[(size_t)sn0 * 256 + off + 32];
        float f10 = FS[(size_t)sn1 * 256 + off], f11 = FS[(size_t)sn1 * 256 + off + 32];
        float f20 = FS[(size_t)sn2 * 256 + off], f21 = FS[(size_t)sn2 * 256 + off + 32];
        float f30 = FS[(size_t)sn3 * 256 + off], f31 = FS[(size_t)sn3 * 256 + off + 32];

        float v, t0, t1, t2, t3;
        v = f00 + fd0; v = (v > 0.f) ? v : SLOPE * v; t0  = v * at0;
        v = f01 + fd1; v = (v > 0.f) ? v : SLOPE * v; t0 += v * at1;
        v = f10 + fd0; v = (v > 0.f) ? v : SLOPE * v; t1  = v * at0;
        v = f11 + fd1; v = (v > 0.f) ? v : SLOPE * v; t1 += v * at1;
        v = f20 + fd0; v = (v > 0.f) ? v : SLOPE * v; t2  = v * at0;
        v = f21 + fd1; v = (v > 0.f) ? v : SLOPE * v; t2 += v * at1;
        v = f30 + fd0; v = (v > 0.f) ? v : SLOPE * v; t3  = v * at0;
        v = f31 + fd1; v = (v > 0.f) ? v : SLOPE * v; t3 += v * at1;

        float e0, e1, e2, e3;
        multi_reduce_exp4(t0, t1, t2, t3, e0, e1, e2, e3);

        den += (e0 + e1) + (e2 + e3);
        s0 += f00 * e0 + f10 * e1 + f20 * e2 + f30 * e3;
        s1 += f01 * e0 + f11 * e1 + f21 * e2 + f31 * e3;
    }
    for (; p < pEnd; p++) {
        int sn = col[p];
        float f0 = FS[(size_t)sn * 256 + off];
        float f1 = FS[(size_t)sn * 256 + off + 32];
        float v0 = f0 + fd0; v0 = (v0 > 0.f) ? v0 : SLOPE * v0;
        float v1 = f1 + fd1; v1 = (v1 > 0.f) ? v1 : SLOPE * v1;
        float t = v0 * at0 + v1 * at1;
        #pragma unroll
        for (int o = 16; o > 0; o >>= 1) t += __shfl_xor_sync(0xffffffffu, t, o);
        float ex = __expf(t);
        den += ex; s0 += f0 * ex; s1 += f1 * ex;
    }

    const float inv = (den > 0.f) ? (1.f / den) : 0.f;
    float o0 = s0 * inv;
    float o1 = s1 * inv;
    if (RES) {
        o0 += resid[(size_t)node * 256 + off];
        o1 += resid[(size_t)node * 256 + off + 32];
    }
    o0 = (o0 > 0.f) ? o0 : expm1f(o0);
    o1 = (o1 > 0.f) ? o1 : expm1f(o1);
    if (WRITE_F32) {
        out[(size_t)node * 256 + off]      = o0;
        out[(size_t)node * 256 + off + 32] = o1;
    }
    __nv_bfloat16 h0 = __float2bfloat16(o0);
    __nv_bfloat16 h1 = __float2bfloat16(o1);
    AH[(size_t)node * 256 + off]      = h0;
    AH[(size_t)node * 256 + off + 32] = h1;
    AL[(size_t)node * 256 + off]      = __float2bfloat16(o0 - __bfloat162float(h0));
    AL[(size_t)node * 256 + off + 32] = __float2bfloat16(o1 - __bfloat162float(h1));
}

// ===========================================================================
// Aggregation, layer 2 (H=6, D=32) with packed reduce + head mean + residual.
// ===========================================================================
__global__ __launch_bounds__(192) void gat_agg_l2_kernel(
    const int* __restrict__ rowptr, const int* __restrict__ col,
    const float* __restrict__ FS, const float* __restrict__ FD,
    const float* __restrict__ attn,
    const float* __restrict__ resm, float* __restrict__ out)
{
    __shared__ float sm[192];
    const int node = blockIdx.x;
    const int w = threadIdx.x / 32;
    const int lane = threadIdx.x & 31;

    const int off = w * 32 + lane;
    const float fd = FD[(size_t)node * 192 + off];
    const float at = __ldg(&attn[off]);

    float s = 0.f, den = 0.f;

    int p = rowptr[node];
    const int pEnd = rowptr[node + 1];

    for (; p + 4 <= pEnd; p += 4) {
        int sn0 = col[p], sn1 = col[p + 1], sn2 = col[p + 2], sn3 = col[p + 3];
        float f0 = FS[(size_t)sn0 * 192 + off];
        float f1 = FS[(size_t)sn1 * 192 + off];
        float f2 = FS[(size_t)sn2 * 192 + off];
        float f3 = FS[(size_t)sn3 * 192 + off];
        float v, t0, t1, t2, t3;
        v = f0 + fd; v = (v > 0.f) ? v : SLOPE * v; t0 = v * at;
        v = f1 + fd; v = (v > 0.f) ? v : SLOPE * v; t1 = v * at;
        v = f2 + fd; v = (v > 0.f) ? v : SLOPE * v; t2 = v * at;
        v = f3 + fd; v = (v > 0.f) ? v : SLOPE * v; t3 = v * at;

        float e0, e1, e2, e3;
        multi_reduce_exp4(t0, t1, t2, t3, e0, e1, e2, e3);

        den += (e0 + e1) + (e2 + e3);
        s += f0 * e0 + f1 * e1 + f2 * e2 + f3 * e3;
    }
    for (; p < pEnd; p++) {
        int sn = col[p];
        float f = FS[(size_t)sn * 192 + off];
        float v = f + fd; v = (v > 0.f) ? v : SLOPE * v;
        float t = v * at;
        #pragma unroll
        for (int o = 16; o > 0; o >>= 1) t += __shfl_xor_sync(0xffffffffu, t, o);
        float ex = __expf(t);
        den += ex; s += f * ex;
    }

    const float inv = (den > 0.f) ? (1.f / den) : 0.f;
    sm[off] = s * inv;
    __syncthreads();

    if (w == 0) {
        float m = 0.f;
        #pragma unroll
        for (int h = 0; h < 6; h++) m += sm[h * 32 + lane];
        out[(size_t)node * 32 + lane] = m * (1.f / 6.f) + resm[(size_t)node * 64 + lane];
    }
}

// ===========================================================================
// Host driver (R13 structure)
// ===========================================================================
extern "C" void kernel_launch(void* const* d_in, const int* in_sizes, int n_in,
                              void* d_out, int out_size)
{
    const float* x   = (const float*)d_in[0];
    const int*   src = (const int*)d_in[1];
    const int*   dst = (const int*)d_in[2];
    const float* W0s = (const float*)d_in[3];
    const float* b0s = (const float*)d_in[4];
    const float* W0d = (const float*)d_in[5];
    const float* b0d = (const float*)d_in[6];
    const float* a0  = (const float*)d_in[7];
    const float* W1s = (const float*)d_in[8];
    const float* b1s = (const float*)d_in[9];
    const float* W1d = (const float*)d_in[10];
    const float* b1d = (const float*)d_in[11];
    const float* a1  = (const float*)d_in[12];
    const float* W2s = (const float*)d_in[13];
    const float* b2s = (const float*)d_in[14];
    const float* W2d = (const float*)d_in[15];
    const float* b2d = (const float*)d_in[16];
    const float* a2  = (const float*)d_in[17];
    const float* Wr2 = (const float*)d_in[18];
    const float* br2 = (const float*)d_in[19];

    const int N = in_sizes[0] / 128;
    const int E = in_sizes[1];

    float *FS, *FD, *HA, *BR2M;
    __nv_bfloat16 *AH, *AL, *WH, *WL;
    int *CNT, *ROWPTR, *CURS, *COL, *BLKSUM;
    cudaGetSymbolAddress((void**)&FS, g_FS);
    cudaGetSymbolAddress((void**)&FD, g_FD);
    cudaGetSymbolAddress((void**)&HA, g_HA);
    cudaGetSymbolAddress((void**)&BR2M, g_BR2M);
    cudaGetSymbolAddress((void**)&AH, g_AH);
    cudaGetSymbolAddress((void**)&AL, g_AL);
    cudaGetSymbolAddress((void**)&WH, g_WH);
    cudaGetSymbolAddress((void**)&WL, g_WL);
    cudaGetSymbolAddress((void**)&CNT, g_CNT);
    cudaGetSymbolAddress((void**)&ROWPTR, g_ROWPTR);
    cudaGetSymbolAddress((void**)&CURS, g_CURS);
    cudaGetSymbolAddress((void**)&COL, g_COL);
    cudaGetSymbolAddress((void**)&BLKSUM, g_BLKSUM);

    float* out = (float*)d_out;

    const int TB = 256;
    const int mTiles = cdiv(N, 128);

    {
        WcP wp;
        wp.W[0] = W0s; wp.W[1] = W0d; wp.W[2] = W1s; wp.W[3] = W1d;
        wp.W[4] = W2s; wp.W[5] = W2d; wp.Wr2 = Wr2; wp.br2 = br2;
        wconv_kernel<<<cdiv(WT_TOTAL, TB), TB>>>(wp, WH, WL, BR2M);
    }
    conv_x_kernel<<<cdiv(N * 128, TB), TB>>>(x, AH, AL, N * 128);
    hist_kernel<<<cdiv(E, TB), TB>>>(dst, CNT, E);
    scan_blk_kernel<<<SCAN_G, SCAN_B>>>(CNT, ROWPTR, BLKSUM, N);

    // ---------------- Layer 0 GEMM: K=128 -> FS, FD ----------------
    {
        MmaP P;
        for (int i = 0; i < 8; i++) { P.selMap[i] = i >> 2; P.colMap[i] = (i & 3) * 64; }
        P.woff[0] = 0;     P.bias[0] = b0s; P.C[0] = FS; P.Cld[0] = 256;
        P.woff[1] = 32768; P.bias[1] = b0d; P.C[1] = FD; P.Cld[1] = 256;
        P.woff[2] = 0;     P.bias[2] = b0s; P.C[2] = FS; P.Cld[2] = 256;
        dim3 grid(mTiles, 8);
        gemm_mma_kernel<<<grid, 256>>>(AH, AL, WH, WL, P, N, 128);
    }

    scan_fix_kernel<<<SCAN_G, SCAN_B>>>(BLKSUM, ROWPTR, CURS, N);
    fill_kernel<<<cdiv(E, TB), TB>>>(src, dst, CURS, COL, E);

    gat_agg_h4d64_kernel<0, 1><<<N, 128>>>(ROWPTR, COL, FS, FD, a0, nullptr, HA, AH, AL);

    // ---------------- Layer 1: K=256 -> FS, FD ----------------
    {
        MmaP P;
        for (int i = 0; i < 8; i++) { P.selMap[i] = i >> 2; P.colMap[i] = (i & 3) * 64; }
        P.woff[0] = 65536;  P.bias[0] = b1s; P.C[0] = FS; P.Cld[0] = 256;
        P.woff[1] = 131072; P.bias[1] = b1d; P.C[1] = FD; P.Cld[1] = 256;
        P.woff[2] = 0;      P.bias[2] = b1s; P.C[2] = FS; P.Cld[2] = 256;
        dim3 grid(mTiles, 8);
        gemm_mma_kernel<<<grid, 256>>>(AH, AL, WH, WL, P, N, 256);
    }
    gat_agg_h4d64_kernel<1, 0><<<N, 128>>>(ROWPTR, COL, FS, FD, a1, HA, nullptr, AH, AL);

    // ---------------- Layer 2: K=256 -> FS, FD (192) + resm (64) ------
    {
        MmaP P;
        const int sm_[7] = {0, 0, 0, 1, 1, 1, 2};
        const int cm_[7] = {0, 64, 128, 0, 64, 128, 0};
        for (int i = 0; i < 7; i++) { P.selMap[i] = sm_[i]; P.colMap[i] = cm_[i]; }
        P.selMap[7] = 0; P.colMap[7] = 0;
        P.woff[0] = 196608; P.bias[0] = b2s;  P.C[0] = FS; P.Cld[0] = 192;
        P.woff[1] = 245760; P.bias[1] = b2d;  P.C[1] = FD; P.Cld[1] = 192;
        P.woff[2] = 294912; P.bias[2] = BR2M; P.C[2] = HA; P.Cld[2] = 64;
        dim3 grid(mTiles, 7);
        gemm_mma_kernel<<<grid, 256>>>(AH, AL, WH, WL, P, N, 256);
    }
    gat_agg_l2_kernel<<<N, 192>>>(ROWPTR, COL, FS, FD, a2, HA, out);
}

// round 16
// speedup vs baseline: 1.1185x; 1.0322x over previous
#include <cuda_runtime.h>
#include <cuda_bf16.h>
#include <cstdint>

// ===========================================================================
// GATv2, 3 layers. N=20000, E=320000.
// R15 baseline (packed multi-reduce aggs, R10 mma GEMM, hierarchical scan)
// + fused prep kernel (conv_x + wconv + hist in one launch).
// ===========================================================================

#define N_MAX   20000
#define NPAD    20096
#define E_MAX   320000
#define SLOPE   0.2f
#define SCAN_B  512
#define SCAN_G  40

__device__ __align__(16) float g_FS[N_MAX * 256];
__device__ __align__(16) float g_FD[N_MAX * 256];
__device__ __align__(16) float g_HA[N_MAX * 256];
__device__ __align__(16) __nv_bfloat16 g_AH[NPAD * 256];
__device__ __align__(16) __nv_bfloat16 g_AL[NPAD * 256];
#define WT_TOTAL 311296
__device__ __align__(16) __nv_bfloat16 g_WH[WT_TOTAL];
__device__ __align__(16) __nv_bfloat16 g_WL[WT_TOTAL];
__device__ __align__(16) float g_BR2M[64];
__device__ int g_CNT[N_MAX];
__device__ int g_ROWPTR[N_MAX + 1];
__device__ int g_CURS[N_MAX];
__device__ int g_COL[E_MAX];
__device__ int g_BLKSUM[SCAN_G];

static inline int cdiv(int a, int b) { return (a + b - 1) / b; }

// ===========================================================================
// Fused prep: conv_x + wconv(+bm) + hist, one grid.
// ===========================================================================
struct PrepP {
    const float* x;
    const float* W[6]; const float* Wr2; const float* br2;
    const int* dst;
    __nv_bfloat16* AH; __nv_bfloat16* AL;
    __nv_bfloat16* WH; __nv_bfloat16* WL;
    float* bm;
    int* cnt;
    int NX; int E;
};

__global__ void prep_kernel(PrepP P) {
    int i = blockIdx.x * blockDim.x + threadIdx.x;
    if (i < 64) {
        float v = 0.f;
        if (i < 32) {
            #pragma unroll
            for (int h = 0; h < 6; h++) v += P.br2[h * 32 + i];
            v *= (1.f / 6.f);
        }
        P.bm[i] = v;
    }
    if (i < P.NX) {
        float v = P.x[i];
        __nv_bfloat16 h = __float2bfloat16(v);
        P.AH[i] = h;
        P.AL[i] = __float2bfloat16(v - __bfloat162float(h));
        return;
    }
    i -= P.NX;
    if (i < WT_TOTAL) {
        const int offs[8] = {0, 32768, 65536, 131072, 196608, 245760, 294912, 311296};
        const int Ks[7]   = {128, 128, 256, 256, 256, 256, 256};
        const int Ms[7]   = {256, 256, 256, 256, 192, 192, 64};
        int j = 0;
        #pragma unroll
        for (int q = 1; q < 7; q++) if (i >= offs[q]) j = q;
        int local = i - offs[j];
        int K = Ks[j];
        int n = local / K, k = local % K;
        float v;
        if (j < 6) {
            v = P.W[j][(size_t)k * Ms[j] + n];
        } else {
            v = 0.f;
            if (n < 32) {
                #pragma unroll
                for (int h = 0; h < 6; h++) v += P.Wr2[(size_t)k * 192 + h * 32 + n];
                v *= (1.f / 6.f);
            }
        }
        __nv_bfloat16 h = __float2bfloat16(v);
        P.WH[i] = h;
        P.WL[i] = __float2bfloat16(v - __bfloat162float(h));
        return;
    }
    i -= WT_TOTAL;
    if (i < P.E) atomicAdd(&P.cnt[P.dst[i]], 1);
}

// ===========================================================================
// Hierarchical scan + fill
// ===========================================================================
__global__ __launch_bounds__(SCAN_B) void scan_blk_kernel(
    int* __restrict__ cnt, int* __restrict__ rowptr,
    int* __restrict__ blksum, int n)
{
    __shared__ int sm[SCAN_B];
    const int t = threadIdx.x;
    const int idx = blockIdx.x * SCAN_B + t;
    int v = (idx < n) ? cnt[idx] : 0;
    sm[t] = v;
    __syncthreads();
    for (int off = 1; off < SCAN_B; off <<= 1) {
        int u = (t >= off) ? sm[t - off] : 0;
        __syncthreads();
        sm[t] += u;
        __syncthreads();
    }
    if (idx < n) {
        rowptr[idx] = sm[t] - v;
        cnt[idx] = 0;
    }
    if (t == SCAN_B - 1) blksum[blockIdx.x] = sm[t];
}

__global__ __launch_bounds__(SCAN_B) void scan_fix_kernel(
    const int* __restrict__ blksum, int* __restrict__ rowptr,
    int* __restrict__ curs, int n)
{
    __shared__ int soff;
    const int b = blockIdx.x;
    const int t = threadIdx.x;
    if (t == 0) {
        int o = 0;
        for (int i = 0; i < b; i++) o += blksum[i];
        soff = o;
        if (b == gridDim.x - 1) rowptr[n] = o + blksum[b];
    }
    __syncthreads();
    const int off = soff;
    const int idx = b * SCAN_B + t;
    if (idx < n) {
        int r = rowptr[idx] + off;
        rowptr[idx] = r;
        curs[idx] = r;
    }
}

__global__ void fill_kernel(const int* __restrict__ src, const int* __restrict__ dst,
                            int* __restrict__ curs, int* __restrict__ col, int E) {
    int e = blockIdx.x * blockDim.x + threadIdx.x;
    if (e < E) {
        int pos = atomicAdd(&curs[dst[e]], 1);
        col[pos] = src[e];
    }
}

// ===========================================================================
// Split-bf16 mma GEMM (R10 config).
// ===========================================================================
#define SPAD 40

struct MmaP {
    int   selMap[8];
    int   colMap[8];
    int   woff[3];
    const float* bias[3];
    float* C[3];
    int   Cld[3];
};

__device__ __forceinline__ void mma_bf16(float d[4], const uint32_t a[4],
                                         const uint32_t b[2]) {
    asm volatile(
        "mma.sync.aligned.m16n8k16.row.col.f32.bf16.bf16.f32 "
        "{%0,%1,%2,%3}, {%4,%5,%6,%7}, {%8,%9}, {%0,%1,%2,%3};"
        : "+f"(d[0]), "+f"(d[1]), "+f"(d[2]), "+f"(d[3])
        : "r"(a[0]), "r"(a[1]), "r"(a[2]), "r"(a[3]), "r"(b[0]), "r"(b[1]));
}

__device__ __forceinline__ void ldsm_x4(uint32_t r[4], const __nv_bfloat16* p) {
    uint32_t a = (uint32_t)__cvta_generic_to_shared(p);
    asm volatile("ldmatrix.sync.aligned.m8n8.x4.shared.b16 {%0,%1,%2,%3}, [%4];"
                 : "=r"(r[0]), "=r"(r[1]), "=r"(r[2]), "=r"(r[3]) : "r"(a));
}

__device__ __forceinline__ void cp16(void* smem, const void* g) {
    uint32_t s = (uint32_t)__cvta_generic_to_shared(smem);
    asm volatile("cp.async.cg.shared.global [%0], [%1], 16;" :: "r"(s), "l"(g));
}
#define CP_COMMIT() asm volatile("cp.async.commit_group;" ::: "memory")

__global__ __launch_bounds__(256) void gemm_mma_kernel(
    const __nv_bfloat16* __restrict__ AH, const __nv_bfloat16* __restrict__ AL,
    const __nv_bfloat16* __restrict__ WHg, const __nv_bfloat16* __restrict__ WLg,
    MmaP P, int Nrows, int K)
{
    __shared__ __align__(16) __nv_bfloat16 sA[2][2][128][SPAD];
    __shared__ __align__(16) __nv_bfloat16 sB[2][2][64][SPAD];

    const int tid  = threadIdx.x;
    const int wid  = tid >> 5;
    const int lane = tid & 31;
    const int wm   = wid & 3;
    const int wn   = wid >> 2;

    const int sel     = P.selMap[blockIdx.y];
    const int colBase = P.colMap[blockIdx.y];
    const int rowBase = blockIdx.x * 128;

    const __nv_bfloat16* __restrict__ WH = WHg + P.woff[sel];
    const __nv_bfloat16* __restrict__ WL = WLg + P.woff[sel];

    float acc[2][4][4];
    #pragma unroll
    for (int i = 0; i < 2; i++)
        #pragma unroll
        for (int j = 0; j < 4; j++)
            #pragma unroll
            for (int q = 0; q < 4; q++) acc[i][j][q] = 0.f;

    const int aRow = (lane & 15);
    const int aColOff = ((lane >> 4) << 3);
    const int bRow = (lane & 7) | ((lane & 16) >> 1);
    const int bColOff = (lane & 8);

    const int nStages = K / 32;

    auto fill = [&](int s, int buf) {
        const int kB = s * 32;
        #pragma unroll
        for (int i = 0; i < 2; i++) {
            int j = tid * 2 + i;
            int r = j >> 2, sl = j & 3;
            cp16(&sA[buf][0][r][sl * 8], &AH[(size_t)(rowBase + r) * K + kB + sl * 8]);
            cp16(&sA[buf][1][r][sl * 8], &AL[(size_t)(rowBase + r) * K + kB + sl * 8]);
        }
        {
            int r = tid >> 2, sl = tid & 3;
            cp16(&sB[buf][0][r][sl * 8], &WH[(size_t)(colBase + r) * K + kB + sl * 8]);
            cp16(&sB[buf][1][r][sl * 8], &WL[(size_t)(colBase + r) * K + kB + sl * 8]);
        }
        CP_COMMIT();
    };

    fill(0, 0);

    for (int s = 0; s < nStages; s++) {
        const int buf = s & 1;
        if (s + 1 < nStages) {
            fill(s + 1, buf ^ 1);
            asm volatile("cp.async.wait_group 1;" ::: "memory");
        } else {
            asm volatile("cp.async.wait_group 0;" ::: "memory");
        }
        __syncthreads();

        #pragma unroll
        for (int ks = 0; ks < 32; ks += 16) {
            uint32_t ah[2][4], al[2][4];
            #pragma unroll
            for (int mt = 0; mt < 2; mt++) {
                const int r = wm * 32 + mt * 16 + aRow;
                const int c = ks + aColOff;
                ldsm_x4(ah[mt], &sA[buf][0][r][c]);
                ldsm_x4(al[mt], &sA[buf][1][r][c]);
            }
            uint32_t bh[4][2], bl[4][2];
            #pragma unroll
            for (int np = 0; np < 2; np++) {
                const int n0 = wn * 32 + np * 16 + bRow;
                const int c = ks + bColOff;
                uint32_t t[4];
                ldsm_x4(t, &sB[buf][0][n0][c]);
                bh[np * 2][0] = t[0];     bh[np * 2][1] = t[1];
                bh[np * 2 + 1][0] = t[2]; bh[np * 2 + 1][1] = t[3];
                ldsm_x4(t, &sB[buf][1][n0][c]);
                bl[np * 2][0] = t[0];     bl[np * 2][1] = t[1];
                bl[np * 2 + 1][0] = t[2]; bl[np * 2 + 1][1] = t[3];
            }
            #pragma unroll
            for (int mt = 0; mt < 2; mt++)
                #pragma unroll
                for (int nt = 0; nt < 4; nt++) {
                    mma_bf16(acc[mt][nt], ah[mt], bh[nt]);
                    mma_bf16(acc[mt][nt], al[mt], bh[nt]);
                    mma_bf16(acc[mt][nt], ah[mt], bl[nt]);
                }
        }
        __syncthreads();
    }

    const int g  = lane >> 2;
    const int t4 = lane & 3;
    float* C = P.C[sel];
    const int Cld = P.Cld[sel];
    const float* bias = P.bias[sel];
    #pragma unroll
    for (int mt = 0; mt < 2; mt++) {
        const int r0 = rowBase + wm * 32 + mt * 16 + g;
        #pragma unroll
        for (int nt = 0; nt < 4; nt++) {
            const int cc = colBase + wn * 32 + nt * 8 + 2 * t4;
            const float b0 = __ldg(&bias[cc]);
            const float b1 = __ldg(&bias[cc + 1]);
            if (r0 < Nrows) {
                float2 v = make_float2(acc[mt][nt][0] + b0, acc[mt][nt][1] + b1);
                *reinterpret_cast<float2*>(&C[(size_t)r0 * Cld + cc]) = v;
            }
            if (r0 + 8 < Nrows) {
                float2 v = make_float2(acc[mt][nt][2] + b0, acc[mt][nt][3] + b1);
                *reinterpret_cast<float2*>(&C[(size_t)(r0 + 8) * Cld + cc]) = v;
            }
        }
    }
}

// ===========================================================================
// Packed 4-way warp reduce + single expf + broadcast. 13 shfl + 1 expf.
// ===========================================================================
__device__ __forceinline__ void multi_reduce_exp4(
    float t0, float t1, float t2, float t3,
    float& e0, float& e1, float& e2, float& e3)
{
    const unsigned m = 0xffffffffu;
    const int lane = threadIdx.x & 31;
    float r0 = t0 + __shfl_xor_sync(m, t0, 1);
    float r1 = t1 + __shfl_xor_sync(m, t1, 1);
    float r2 = t2 + __shfl_xor_sync(m, t2, 1);
    float r3 = t3 + __shfl_xor_sync(m, t3, 1);
    float p = (lane & 1) ? r1 : r0;
    float q = (lane & 1) ? r3 : r2;
    p += __shfl_xor_sync(m, p, 2);
    q += __shfl_xor_sync(m, q, 2);
    float u = (lane & 2) ? q : p;
    u += __shfl_xor_sync(m, u, 4);
    u += __shfl_xor_sync(m, u, 8);
    u += __shfl_xor_sync(m, u, 16);
    float ex = __expf(u);
    e0 = __shfl_sync(m, ex, 0);
    e1 = __shfl_sync(m, ex, 1);
    e2 = __shfl_sync(m, ex, 2);
    e3 = __shfl_sync(m, ex, 3);
}

// ===========================================================================
// Aggregation, layers 0/1 (H=4, D=64), unroll 4 with packed reduce.
// ===========================================================================
template <int RES, int WRITE_F32>
__global__ __launch_bounds__(128) void gat_agg_h4d64_kernel(
    const int* __restrict__ rowptr, const int* __restrict__ col,
    const float* __restrict__ FS, const float* __restrict__ FD,
    const float* __restrict__ attn,
    const float* __restrict__ resid, float* __restrict__ out,
    __nv_bfloat16* __restrict__ AH, __nv_bfloat16* __restrict__ AL)
{
    const int node = blockIdx.x;
    const int w = threadIdx.x >> 5;
    const int lane = threadIdx.x & 31;

    const int off = w * 64 + lane;
    const float fd0 = FD[(size_t)node * 256 + off];
    const float fd1 = FD[(size_t)node * 256 + off + 32];
    const float at0 = __ldg(&attn[w * 64 + lane]);
    const float at1 = __ldg(&attn[w * 64 + lane + 32]);

    float s0 = 0.f, s1 = 0.f, den = 0.f;

    int p = rowptr[node];
    const int pEnd = rowptr[node + 1];

    for (; p + 4 <= pEnd; p += 4) {
        int sn0 = col[p], sn1 = col[p + 1], sn2 = col[p + 2], sn3 = col[p + 3];
        float f00 = FS[(size_t)sn0 * 256 + off], f01 = FS[(size_t)sn0 * 256 + off + 32];
        float f10 = FS[(size_t)sn1 * 256 + off], f11 = FS[(size_t)sn1 * 256 + off + 32];
        float f20 = FS[(size_t)sn2 * 256 + off], f21 = FS[(size_t)sn2 * 256 + off + 32];
        float f30 = FS[(size_t)sn3 * 256 + off], f31 = FS[(size_t)sn3 * 256 + off + 32];

        float v, t0, t1, t2, t3;
        v = f00 + fd0; v = (v > 0.f) ? v : SLOPE * v; t0  = v * at0;
        v = f01 + fd1; v = (v > 0.f) ? v : SLOPE * v; t0 += v * at1;
        v = f10 + fd0; v = (v > 0.f) ? v : SLOPE * v; t1  = v * at0;
        v = f11 + fd1; v = (v > 0.f) ? v : SLOPE * v; t1 += v * at1;
        v = f20 + fd0; v = (v > 0.f) ? v : SLOPE * v; t2  = v * at0;
        v = f21 + fd1; v = (v > 0.f) ? v : SLOPE * v; t2 += v * at1;
        v = f30 + fd0; v = (v > 0.f) ? v : SLOPE * v; t3  = v * at0;
        v = f31 + fd1; v = (v > 0.f) ? v : SLOPE * v; t3 += v * at1;

        float e0, e1, e2, e3;
        multi_reduce_exp4(t0, t1, t2, t3, e0, e1, e2, e3);

        den += (e0 + e1) + (e2 + e3);
        s0 += f00 * e0 + f10 * e1 + f20 * e2 + f30 * e3;
        s1 += f01 * e0 + f11 * e1 + f21 * e2 + f31 * e3;
    }
    for (; p < pEnd; p++) {
        int sn = col[p];
        float f0 = FS[(size_t)sn * 256 + off];
        float f1 = FS[(size_t)sn * 256 + off + 32];
        float v0 = f0 + fd0; v0 = (v0 > 0.f) ? v0 : SLOPE * v0;
        float v1 = f1 + fd1; v1 = (v1 > 0.f) ? v1 : SLOPE * v1;
        float t = v0 * at0 + v1 * at1;
        #pragma unroll
        for (int o = 16; o > 0; o >>= 1) t += __shfl_xor_sync(0xffffffffu, t, o);
        float ex = __expf(t);
        den += ex; s0 += f0 * ex; s1 += f1 * ex;
    }

    const float inv = (den > 0.f) ? (1.f / den) : 0.f;
    float o0 = s0 * inv;
    float o1 = s1 * inv;
    if (RES) {
        o0 += resid[(size_t)node * 256 + off];
        o1 += resid[(size_t)node * 256 + off + 32];
    }
    o0 = (o0 > 0.f) ? o0 : expm1f(o0);
    o1 = (o1 > 0.f) ? o1 : expm1f(o1);
    if (WRITE_F32) {
        out[(size_t)node * 256 + off]      = o0;
        out[(size_t)node * 256 + off + 32] = o1;
    }
    __nv_bfloat16 h0 = __float2bfloat16(o0);
    __nv_bfloat16 h1 = __float2bfloat16(o1);
    AH[(size_t)node * 256 + off]      = h0;
    AH[(size_t)node * 256 + off + 32] = h1;
    AL[(size_t)node * 256 + off]      = __float2bfloat16(o0 - __bfloat162float(h0));
    AL[(size_t)node * 256 + off + 32] = __float2bfloat16(o1 - __bfloat162float(h1));
}

// ===========================================================================
// Aggregation, layer 2 (H=6, D=32) with packed reduce + head mean + residual.
// ===========================================================================
__global__ __launch_bounds__(192) void gat_agg_l2_kernel(
    const int* __restrict__ rowptr, const int* __restrict__ col,
    const float* __restrict__ FS, const float* __restrict__ FD,
    const float* __restrict__ attn,
    const float* __restrict__ resm, float* __restrict__ out)
{
    __shared__ float sm[192];
    const int node = blockIdx.x;
    const int w = threadIdx.x / 32;
    const int lane = threadIdx.x & 31;

    const int off = w * 32 + lane;
    const float fd = FD[(size_t)node * 192 + off];
    const float at = __ldg(&attn[off]);

    float s = 0.f, den = 0.f;

    int p = rowptr[node];
    const int pEnd = rowptr[node + 1];

    for (; p + 4 <= pEnd; p += 4) {
        int sn0 = col[p], sn1 = col[p + 1], sn2 = col[p + 2], sn3 = col[p + 3];
        float f0 = FS[(size_t)sn0 * 192 + off];
        float f1 = FS[(size_t)sn1 * 192 + off];
        float f2 = FS[(size_t)sn2 * 192 + off];
        float f3 = FS[(size_t)sn3 * 192 + off];
        float v, t0, t1, t2, t3;
        v = f0 + fd; v = (v > 0.f) ? v : SLOPE * v; t0 = v * at;
        v = f1 + fd; v = (v > 0.f) ? v : SLOPE * v; t1 = v * at;
        v = f2 + fd; v = (v > 0.f) ? v : SLOPE * v; t2 = v * at;
        v = f3 + fd; v = (v > 0.f) ? v : SLOPE * v; t3 = v * at;

        float e0, e1, e2, e3;
        multi_reduce_exp4(t0, t1, t2, t3, e0, e1, e2, e3);

        den += (e0 + e1) + (e2 + e3);
        s += f0 * e0 + f1 * e1 + f2 * e2 + f3 * e3;
    }
    for (; p < pEnd; p++) {
        int sn = col[p];
        float f = FS[(size_t)sn * 192 + off];
        float v = f + fd; v = (v > 0.f) ? v : SLOPE * v;
        float t = v * at;
        #pragma unroll
        for (int o = 16; o > 0; o >>= 1) t += __shfl_xor_sync(0xffffffffu, t, o);
        float ex = __expf(t);
        den += ex; s += f * ex;
    }

    const float inv = (den > 0.f) ? (1.f / den) : 0.f;
    sm[off] = s * inv;
    __syncthreads();

    if (w == 0) {
        float m = 0.f;
        #pragma unroll
        for (int h = 0; h < 6; h++) m += sm[h * 32 + lane];
        out[(size_t)node * 32 + lane] = m * (1.f / 6.f) + resm[(size_t)node * 64 + lane];
    }
}

// ===========================================================================
// Host driver
// ===========================================================================
extern "C" void kernel_launch(void* const* d_in, const int* in_sizes, int n_in,
                              void* d_out, int out_size)
{
    const float* x   = (const float*)d_in[0];
    const int*   src = (const int*)d_in[1];
    const int*   dst = (const int*)d_in[2];
    const float* W0s = (const float*)d_in[3];
    const float* b0s = (const float*)d_in[4];
    const float* W0d = (const float*)d_in[5];
    const float* b0d = (const float*)d_in[6];
    const float* a0  = (const float*)d_in[7];
    const float* W1s = (const float*)d_in[8];
    const float* b1s = (const float*)d_in[9];
    const float* W1d = (const float*)d_in[10];
    const float* b1d = (const float*)d_in[11];
    const float* a1  = (const float*)d_in[12];
    const float* W2s = (const float*)d_in[13];
    const float* b2s = (const float*)d_in[14];
    const float* W2d = (const float*)d_in[15];
    const float* b2d = (const float*)d_in[16];
    const float* a2  = (const float*)d_in[17];
    const float* Wr2 = (const float*)d_in[18];
    const float* br2 = (const float*)d_in[19];

    const int N = in_sizes[0] / 128;
    const int E = in_sizes[1];

    float *FS, *FD, *HA, *BR2M;
    __nv_bfloat16 *AH, *AL, *WH, *WL;
    int *CNT, *ROWPTR, *CURS, *COL, *BLKSUM;
    cudaGetSymbolAddress((void**)&FS, g_FS);
    cudaGetSymbolAddress((void**)&FD, g_FD);
    cudaGetSymbolAddress((void**)&HA, g_HA);
    cudaGetSymbolAddress((void**)&BR2M, g_BR2M);
    cudaGetSymbolAddress((void**)&AH, g_AH);
    cudaGetSymbolAddress((void**)&AL, g_AL);
    cudaGetSymbolAddress((void**)&WH, g_WH);
    cudaGetSymbolAddress((void**)&WL, g_WL);
    cudaGetSymbolAddress((void**)&CNT, g_CNT);
    cudaGetSymbolAddress((void**)&ROWPTR, g_ROWPTR);
    cudaGetSymbolAddress((void**)&CURS, g_CURS);
    cudaGetSymbolAddress((void**)&COL, g_COL);
    cudaGetSymbolAddress((void**)&BLKSUM, g_BLKSUM);

    float* out = (float*)d_out;

    const int TB = 256;
    const int mTiles = cdiv(N, 128);

    // order: prep(1) scan_blk(2) scan_fix(3) gemm0(4=profiled) fill(5) agg0(6)...
    {
        PrepP pp;
        pp.x = x;
        pp.W[0] = W0s; pp.W[1] = W0d; pp.W[2] = W1s; pp.W[3] = W1d;
        pp.W[4] = W2s; pp.W[5] = W2d; pp.Wr2 = Wr2; pp.br2 = br2;
        pp.dst = dst;
        pp.AH = AH; pp.AL = AL; pp.WH = WH; pp.WL = WL;
        pp.bm = BR2M; pp.cnt = CNT;
        pp.NX = N * 128; pp.E = E;
        const int total = pp.NX + WT_TOTAL + E;
        prep_kernel<<<cdiv(total, TB), TB>>>(pp);
    }
    scan_blk_kernel<<<SCAN_G, SCAN_B>>>(CNT, ROWPTR, BLKSUM, N);
    scan_fix_kernel<<<SCAN_G, SCAN_B>>>(BLKSUM, ROWPTR, CURS, N);

    // ---------------- Layer 0 GEMM: K=128 -> FS, FD ----------------
    {
        MmaP P;
        for (int i = 0; i < 8; i++) { P.selMap[i] = i >> 2; P.colMap[i] = (i & 3) * 64; }
        P.woff[0] = 0;     P.bias[0] = b0s; P.C[0] = FS; P.Cld[0] = 256;
        P.woff[1] = 32768; P.bias[1] = b0d; P.C[1] = FD; P.Cld[1] = 256;
        P.woff[2] = 0;     P.bias[2] = b0s; P.C[2] = FS; P.Cld[2] = 256;
        dim3 grid(mTiles, 8);
        gemm_mma_kernel<<<grid, 256>>>(AH, AL, WH, WL, P, N, 128);
    }

    fill_kernel<<<cdiv(E, TB), TB>>>(src, dst, CURS, COL, E);

    gat_agg_h4d64_kernel<0, 1><<<N, 128>>>(ROWPTR, COL, FS, FD, a0, nullptr, HA, AH, AL);

    // ---------------- Layer 1: K=256 -> FS, FD ----------------
    {
        MmaP P;
        for (int i = 0; i < 8; i++) { P.selMap[i] = i >> 2; P.colMap[i] = (i & 3) * 64; }
        P.woff[0] = 65536;  P.bias[0] = b1s; P.C[0] = FS; P.Cld[0] = 256;
        P.woff[1] = 131072; P.bias[1] = b1d; P.C[1] = FD; P.Cld[1] = 256;
        P.woff[2] = 0;      P.bias[2] = b1s; P.C[2] = FS; P.Cld[2] = 256;
        dim3 grid(mTiles, 8);
        gemm_mma_kernel<<<grid, 256>>>(AH, AL, WH, WL, P, N, 256);
    }
    gat_agg_h4d64_kernel<1, 0><<<N, 128>>>(ROWPTR, COL, FS, FD, a1, HA, nullptr, AH, AL);

    // ---------------- Layer 2: K=256 -> FS, FD (192) + resm (64) ------
    {
        MmaP P;
        const int sm_[7] = {0, 0, 0, 1, 1, 1, 2};
        const int cm_[7] = {0, 64, 128, 0, 64, 128, 0};
        for (int i = 0; i < 7; i++) { P.selMap[i] = sm_[i]; P.colMap[i] = cm_[i]; }
        P.selMap[7] = 0; P.colMap[7] = 0;
        P.woff[0] = 196608; P.bias[0] = b2s;  P.C[0] = FS; P.Cld[0] = 192;
        P.woff[1] = 245760; P.bias[1] = b2d;  P.C[1] = FD; P.Cld[1] = 192;
        P.woff[2] = 294912; P.bias[2] = BR2M; P.C[2] = HA; P.Cld[2] = 64;
        dim3 grid(mTiles, 7);
        gemm_mma_kernel<<<grid, 256>>>(AH, AL, WH, WL, P, N, 256);
    }
    gat_agg_l2_kernel<<<N, 192>>>(ROWPTR, COL, FS, FD, a2, HA, out);
}

// round 17
// speedup vs baseline: 1.1257x; 1.0064x over previous
#include <cuda_runtime.h>
#include <cuda_bf16.h>
#include <cstdint>

// ===========================================================================
// GATv2, 3 layers. N=20000, E=320000.
// R16 baseline + 3-stage cp.async ring in the mma GEMM (1 sync per stage).
// ===========================================================================

#define N_MAX   20000
#define NPAD    20096
#define E_MAX   320000
#define SLOPE   0.2f
#define SCAN_B  512
#define SCAN_G  40

__device__ __align__(16) float g_FS[N_MAX * 256];
__device__ __align__(16) float g_FD[N_MAX * 256];
__device__ __align__(16) float g_HA[N_MAX * 256];
__device__ __align__(16) __nv_bfloat16 g_AH[NPAD * 256];
__device__ __align__(16) __nv_bfloat16 g_AL[NPAD * 256];
#define WT_TOTAL 311296
__device__ __align__(16) __nv_bfloat16 g_WH[WT_TOTAL];
__device__ __align__(16) __nv_bfloat16 g_WL[WT_TOTAL];
__device__ __align__(16) float g_BR2M[64];
__device__ int g_CNT[N_MAX];
__device__ int g_ROWPTR[N_MAX + 1];
__device__ int g_CURS[N_MAX];
__device__ int g_COL[E_MAX];
__device__ int g_BLKSUM[SCAN_G];

static inline int cdiv(int a, int b) { return (a + b - 1) / b; }

// ===========================================================================
// Fused prep: conv_x + wconv(+bm) + hist, one grid.
// ===========================================================================
struct PrepP {
    const float* x;
    const float* W[6]; const float* Wr2; const float* br2;
    const int* dst;
    __nv_bfloat16* AH; __nv_bfloat16* AL;
    __nv_bfloat16* WH; __nv_bfloat16* WL;
    float* bm;
    int* cnt;
    int NX; int E;
};

__global__ void prep_kernel(PrepP P) {
    int i = blockIdx.x * blockDim.x + threadIdx.x;
    if (i < 64) {
        float v = 0.f;
        if (i < 32) {
            #pragma unroll
            for (int h = 0; h < 6; h++) v += P.br2[h * 32 + i];
            v *= (1.f / 6.f);
        }
        P.bm[i] = v;
    }
    if (i < P.NX) {
        float v = P.x[i];
        __nv_bfloat16 h = __float2bfloat16(v);
        P.AH[i] = h;
        P.AL[i] = __float2bfloat16(v - __bfloat162float(h));
        return;
    }
    i -= P.NX;
    if (i < WT_TOTAL) {
        const int offs[8] = {0, 32768, 65536, 131072, 196608, 245760, 294912, 311296};
        const int Ks[7]   = {128, 128, 256, 256, 256, 256, 256};
        const int Ms[7]   = {256, 256, 256, 256, 192, 192, 64};
        int j = 0;
        #pragma unroll
        for (int q = 1; q < 7; q++) if (i >= offs[q]) j = q;
        int local = i - offs[j];
        int K = Ks[j];
        int n = local / K, k = local % K;
        float v;
        if (j < 6) {
            v = P.W[j][(size_t)k * Ms[j] + n];
        } else {
            v = 0.f;
            if (n < 32) {
                #pragma unroll
                for (int h = 0; h < 6; h++) v += P.Wr2[(size_t)k * 192 + h * 32 + n];
                v *= (1.f / 6.f);
            }
        }
        __nv_bfloat16 h = __float2bfloat16(v);
        P.WH[i] = h;
        P.WL[i] = __float2bfloat16(v - __bfloat162float(h));
        return;
    }
    i -= WT_TOTAL;
    if (i < P.E) atomicAdd(&P.cnt[P.dst[i]], 1);
}

// ===========================================================================
// Hierarchical scan + fill
// ===========================================================================
__global__ __launch_bounds__(SCAN_B) void scan_blk_kernel(
    int* __restrict__ cnt, int* __restrict__ rowptr,
    int* __restrict__ blksum, int n)
{
    __shared__ int sm[SCAN_B];
    const int t = threadIdx.x;
    const int idx = blockIdx.x * SCAN_B + t;
    int v = (idx < n) ? cnt[idx] : 0;
    sm[t] = v;
    __syncthreads();
    for (int off = 1; off < SCAN_B; off <<= 1) {
        int u = (t >= off) ? sm[t - off] : 0;
        __syncthreads();
        sm[t] += u;
        __syncthreads();
    }
    if (idx < n) {
        rowptr[idx] = sm[t] - v;
        cnt[idx] = 0;
    }
    if (t == SCAN_B - 1) blksum[blockIdx.x] = sm[t];
}

__global__ __launch_bounds__(SCAN_B) void scan_fix_kernel(
    const int* __restrict__ blksum, int* __restrict__ rowptr,
    int* __restrict__ curs, int n)
{
    __shared__ int soff;
    const int b = blockIdx.x;
    const int t = threadIdx.x;
    if (t == 0) {
        int o = 0;
        for (int i = 0; i < b; i++) o += blksum[i];
        soff = o;
        if (b == gridDim.x - 1) rowptr[n] = o + blksum[b];
    }
    __syncthreads();
    const int off = soff;
    const int idx = b * SCAN_B + t;
    if (idx < n) {
        int r = rowptr[idx] + off;
        rowptr[idx] = r;
        curs[idx] = r;
    }
}

__global__ void fill_kernel(const int* __restrict__ src, const int* __restrict__ dst,
                            int* __restrict__ curs, int* __restrict__ col, int E) {
    int e = blockIdx.x * blockDim.x + threadIdx.x;
    if (e < E) {
        int pos = atomicAdd(&curs[dst[e]], 1);
        col[pos] = src[e];
    }
}

// ===========================================================================
// Split-bf16 mma GEMM: 3-stage cp.async ring, 1 sync per stage.
// CTA 128x64, 256 thr / 8 warps (4m x 2n), warp tile 32x32, K staged 32.
// D = Ah*Bh + Al*Bh + Ah*Bl (fp32 accum).
// ===========================================================================
#define SPAD 40

struct MmaP {
    int   selMap[8];
    int   colMap[8];
    int   woff[3];
    const float* bias[3];
    float* C[3];
    int   Cld[3];
};

__device__ __forceinline__ void mma_bf16(float d[4], const uint32_t a[4],
                                         const uint32_t b[2]) {
    asm volatile(
        "mma.sync.aligned.m16n8k16.row.col.f32.bf16.bf16.f32 "
        "{%0,%1,%2,%3}, {%4,%5,%6,%7}, {%8,%9}, {%0,%1,%2,%3};"
        : "+f"(d[0]), "+f"(d[1]), "+f"(d[2]), "+f"(d[3])
        : "r"(a[0]), "r"(a[1]), "r"(a[2]), "r"(a[3]), "r"(b[0]), "r"(b[1]));
}

__device__ __forceinline__ void ldsm_x4(uint32_t r[4], const __nv_bfloat16* p) {
    uint32_t a = (uint32_t)__cvta_generic_to_shared(p);
    asm volatile("ldmatrix.sync.aligned.m8n8.x4.shared.b16 {%0,%1,%2,%3}, [%4];"
                 : "=r"(r[0]), "=r"(r[1]), "=r"(r[2]), "=r"(r[3]) : "r"(a));
}

__device__ __forceinline__ void cp16(void* smem, const void* g) {
    uint32_t s = (uint32_t)__cvta_generic_to_shared(smem);
    asm volatile("cp.async.cg.shared.global [%0], [%1], 16;" :: "r"(s), "l"(g));
}
#define CP_COMMIT() asm volatile("cp.async.commit_group;" ::: "memory")

__global__ __launch_bounds__(256) void gemm_mma_kernel(
    const __nv_bfloat16* __restrict__ AH, const __nv_bfloat16* __restrict__ AL,
    const __nv_bfloat16* __restrict__ WHg, const __nv_bfloat16* __restrict__ WLg,
    MmaP P, int Nrows, int K)
{
    __shared__ __align__(16) __nv_bfloat16 sA[3][2][128][SPAD];
    __shared__ __align__(16) __nv_bfloat16 sB[3][2][64][SPAD];

    const int tid  = threadIdx.x;
    const int wid  = tid >> 5;
    const int lane = tid & 31;
    const int wm   = wid & 3;
    const int wn   = wid >> 2;

    const int sel     = P.selMap[blockIdx.y];
    const int colBase = P.colMap[blockIdx.y];
    const int rowBase = blockIdx.x * 128;

    const __nv_bfloat16* __restrict__ WH = WHg + P.woff[sel];
    const __nv_bfloat16* __restrict__ WL = WLg + P.woff[sel];

    float acc[2][4][4];
    #pragma unroll
    for (int i = 0; i < 2; i++)
        #pragma unroll
        for (int j = 0; j < 4; j++)
            #pragma unroll
            for (int q = 0; q < 4; q++) acc[i][j][q] = 0.f;

    const int aRow = (lane & 15);
    const int aColOff = ((lane >> 4) << 3);
    const int bRow = (lane & 7) | ((lane & 16) >> 1);
    const int bColOff = (lane & 8);

    const int nStages = K / 32;

    auto fill = [&](int s, int buf) {
        const int kB = s * 32;
        #pragma unroll
        for (int i = 0; i < 2; i++) {
            int j = tid * 2 + i;
            int r = j >> 2, sl = j & 3;
            cp16(&sA[buf][0][r][sl * 8], &AH[(size_t)(rowBase + r) * K + kB + sl * 8]);
            cp16(&sA[buf][1][r][sl * 8], &AL[(size_t)(rowBase + r) * K + kB + sl * 8]);
        }
        {
            int r = tid >> 2, sl = tid & 3;
            cp16(&sB[buf][0][r][sl * 8], &WH[(size_t)(colBase + r) * K + kB + sl * 8]);
            cp16(&sB[buf][1][r][sl * 8], &WL[(size_t)(colBase + r) * K + kB + sl * 8]);
        }
        CP_COMMIT();
    };

    // prologue: 2 stages in flight
    fill(0, 0);
    if (nStages > 1) fill(1, 1);

    for (int s = 0; s < nStages; s++) {
        const int buf = s % 3;
        // wait for group s (groups complete in order; allow 1 pending if more issued)
        if (s + 1 < nStages) {
            asm volatile("cp.async.wait_group 1;" ::: "memory");
        } else {
            asm volatile("cp.async.wait_group 0;" ::: "memory");
        }
        __syncthreads();   // data visible; all warps done with buf (s+2)%3 reads from iter s-1

        #pragma unroll
        for (int ks = 0; ks < 32; ks += 16) {
            uint32_t ah[2][4], al[2][4];
            #pragma unroll
            for (int mt = 0; mt < 2; mt++) {
                const int r = wm * 32 + mt * 16 + aRow;
                const int c = ks + aColOff;
                ldsm_x4(ah[mt], &sA[buf][0][r][c]);
                ldsm_x4(al[mt], &sA[buf][1][r][c]);
            }
            uint32_t bh[4][2], bl[4][2];
            #pragma unroll
            for (int np = 0; np < 2; np++) {
                const int n0 = wn * 32 + np * 16 + bRow;
                const int c = ks + bColOff;
                uint32_t t[4];
                ldsm_x4(t, &sB[buf][0][n0][c]);
                bh[np * 2][0] = t[0];     bh[np * 2][1] = t[1];
                bh[np * 2 + 1][0] = t[2]; bh[np * 2 + 1][1] = t[3];
                ldsm_x4(t, &sB[buf][1][n0][c]);
                bl[np * 2][0] = t[0];     bl[np * 2][1] = t[1];
                bl[np * 2 + 1][0] = t[2]; bl[np * 2 + 1][1] = t[3];
            }
            #pragma unroll
            for (int mt = 0; mt < 2; mt++)
                #pragma unroll
                for (int nt = 0; nt < 4; nt++) {
                    mma_bf16(acc[mt][nt], ah[mt], bh[nt]);
                    mma_bf16(acc[mt][nt], al[mt], bh[nt]);
                    mma_bf16(acc[mt][nt], ah[mt], bl[nt]);
                }
        }

        // issue fill for stage s+2 into buf (s+2)%3 — last read in iter s-1,
        // protected by the sync at top of this iteration.
        if (s + 2 < nStages) fill(s + 2, (s + 2) % 3);
    }

    const int g  = lane >> 2;
    const int t4 = lane & 3;
    float* C = P.C[sel];
    const int Cld = P.Cld[sel];
    const float* bias = P.bias[sel];
    #pragma unroll
    for (int mt = 0; mt < 2; mt++) {
        const int r0 = rowBase + wm * 32 + mt * 16 + g;
        #pragma unroll
        for (int nt = 0; nt < 4; nt++) {
            const int cc = colBase + wn * 32 + nt * 8 + 2 * t4;
            const float b0 = __ldg(&bias[cc]);
            const float b1 = __ldg(&bias[cc + 1]);
            if (r0 < Nrows) {
                float2 v = make_float2(acc[mt][nt][0] + b0, acc[mt][nt][1] + b1);
                *reinterpret_cast<float2*>(&C[(size_t)r0 * Cld + cc]) = v;
            }
            if (r0 + 8 < Nrows) {
                float2 v = make_float2(acc[mt][nt][2] + b0, acc[mt][nt][3] + b1);
                *reinterpret_cast<float2*>(&C[(size_t)(r0 + 8) * Cld + cc]) = v;
            }
        }
    }
}

// ===========================================================================
// Packed 4-way warp reduce + single expf + broadcast. 13 shfl + 1 expf.
// ===========================================================================
__device__ __forceinline__ void multi_reduce_exp4(
    float t0, float t1, float t2, float t3,
    float& e0, float& e1, float& e2, float& e3)
{
    const unsigned m = 0xffffffffu;
    const int lane = threadIdx.x & 31;
    float r0 = t0 + __shfl_xor_sync(m, t0, 1);
    float r1 = t1 + __shfl_xor_sync(m, t1, 1);
    float r2 = t2 + __shfl_xor_sync(m, t2, 1);
    float r3 = t3 + __shfl_xor_sync(m, t3, 1);
    float p = (lane & 1) ? r1 : r0;
    float q = (lane & 1) ? r3 : r2;
    p += __shfl_xor_sync(m, p, 2);
    q += __shfl_xor_sync(m, q, 2);
    float u = (lane & 2) ? q : p;
    u += __shfl_xor_sync(m, u, 4);
    u += __shfl_xor_sync(m, u, 8);
    u += __shfl_xor_sync(m, u, 16);
    float ex = __expf(u);
    e0 = __shfl_sync(m, ex, 0);
    e1 = __shfl_sync(m, ex, 1);
    e2 = __shfl_sync(m, ex, 2);
    e3 = __shfl_sync(m, ex, 3);
}

// ===========================================================================
// Aggregation, layers 0/1 (H=4, D=64), unroll 4 with packed reduce.
// ===========================================================================
template <int RES, int WRITE_F32>
__global__ __launch_bounds__(128) void gat_agg_h4d64_kernel(
    const int* __restrict__ rowptr, const int* __restrict__ col,
    const float* __restrict__ FS, const float* __restrict__ FD,
    const float* __restrict__ attn,
    const float* __restrict__ resid, float* __restrict__ out,
    __nv_bfloat16* __restrict__ AH, __nv_bfloat16* __restrict__ AL)
{
    const int node = blockIdx.x;
    const int w = threadIdx.x >> 5;
    const int lane = threadIdx.x & 31;

    const int off = w * 64 + lane;
    const float fd0 = FD[(size_t)node * 256 + off];
    const float fd1 = FD[(size_t)node * 256 + off + 32];
    const float at0 = __ldg(&attn[w * 64 + lane]);
    const float at1 = __ldg(&attn[w * 64 + lane + 32]);

    float s0 = 0.f, s1 = 0.f, den = 0.f;

    int p = rowptr[node];
    const int pEnd = rowptr[node + 1];

    for (; p + 4 <= pEnd; p += 4) {
        int sn0 = col[p], sn1 = col[p + 1], sn2 = col[p + 2], sn3 = col[p + 3];
        float f00 = FS[(size_t)sn0 * 256 + off], f01 = FS[(size_t)sn0 * 256 + off + 32];
        float f10 = FS[(size_t)sn1 * 256 + off], f11 = FS[(size_t)sn1 * 256 + off + 32];
        float f20 = FS[(size_t)sn2 * 256 + off], f21 = FS[(size_t)sn2 * 256 + off + 32];
        float f30 = FS[(size_t)sn3 * 256 + off], f31 = FS[(size_t)sn3 * 256 + off + 32];

        float v, t0, t1, t2, t3;
        v = f00 + fd0; v = (v > 0.f) ? v : SLOPE * v; t0  = v * at0;
        v = f01 + fd1; v = (v > 0.f) ? v : SLOPE * v; t0 += v * at1;
        v = f10 + fd0; v = (v > 0.f) ? v : SLOPE * v; t1  = v * at0;
        v = f11 + fd1; v = (v > 0.f) ? v : SLOPE * v; t1 += v * at1;
        v = f20 + fd0; v = (v > 0.f) ? v : SLOPE * v; t2  = v * at0;
        v = f21 + fd1; v = (v > 0.f) ? v : SLOPE * v; t2 += v * at1;
        v = f30 + fd0; v = (v > 0.f) ? v : SLOPE * v; t3  = v * at0;
        v = f31 + fd1; v = (v > 0.f) ? v : SLOPE * v; t3 += v * at1;

        float e0, e1, e2, e3;
        multi_reduce_exp4(t0, t1, t2, t3, e0, e1, e2, e3);

        den += (e0 + e1) + (e2 + e3);
        s0 += f00 * e0 + f10 * e1 + f20 * e2 + f30 * e3;
        s1 += f01 * e0 + f11 * e1 + f21 * e2 + f31 * e3;
    }
    for (; p < pEnd; p++) {
        int sn = col[p];
        float f0 = FS[(size_t)sn * 256 + off];
        float f1 = FS[(size_t)sn * 256 + off + 32];
        float v0 = f0 + fd0; v0 = (v0 > 0.f) ? v0 : SLOPE * v0;
        float v1 = f1 + fd1; v1 = (v1 > 0.f) ? v1 : SLOPE * v1;
        float t = v0 * at0 + v1 * at1;
        #pragma unroll
        for (int o = 16; o > 0; o >>= 1) t += __shfl_xor_sync(0xffffffffu, t, o);
        float ex = __expf(t);
        den += ex; s0 += f0 * ex; s1 += f1 * ex;
    }

    const float inv = (den > 0.f) ? (1.f / den) : 0.f;
    float o0 = s0 * inv;
    float o1 = s1 * inv;
    if (RES) {
        o0 += resid[(size_t)node * 256 + off];
        o1 += resid[(size_t)node * 256 + off + 32];
    }
    o0 = (o0 > 0.f) ? o0 : expm1f(o0);
    o1 = (o1 > 0.f) ? o1 : expm1f(o1);
    if (WRITE_F32) {
        out[(size_t)node * 256 + off]      = o0;
        out[(size_t)node * 256 + off + 32] = o1;
    }
    __nv_bfloat16 h0 = __float2bfloat16(o0);
    __nv_bfloat16 h1 = __float2bfloat16(o1);
    AH[(size_t)node * 256 + off]      = h0;
    AH[(size_t)node * 256 + off + 32] = h1;
    AL[(size_t)node * 256 + off]      = __float2bfloat16(o0 - __bfloat162float(h0));
    AL[(size_t)node * 256 + off + 32] = __float2bfloat16(o1 - __bfloat162float(h1));
}

// ===========================================================================
// Aggregation, layer 2 (H=6, D=32) with packed reduce + head mean + residual.
// ===========================================================================
__global__ __launch_bounds__(192) void gat_agg_l2_kernel(
    const int* __restrict__ rowptr, const int* __restrict__ col,
    const float* __restrict__ FS, const float* __restrict__ FD,
    const float* __restrict__ attn,
    const float* __restrict__ resm, float* __restrict__ out)
{
    __shared__ float sm[192];
    const int node = blockIdx.x;
    const int w = threadIdx.x / 32;
    const int lane = threadIdx.x & 31;

    const int off = w * 32 + lane;
    const float fd = FD[(size_t)node * 192 + off];
    const float at = __ldg(&attn[off]);

    float s = 0.f, den = 0.f;

    int p = rowptr[node];
    const int pEnd = rowptr[node + 1];

    for (; p + 4 <= pEnd; p += 4) {
        int sn0 = col[p], sn1 = col[p + 1], sn2 = col[p + 2], sn3 = col[p + 3];
        float f0 = FS[(size_t)sn0 * 192 + off];
        float f1 = FS[(size_t)sn1 * 192 + off];
        float f2 = FS[(size_t)sn2 * 192 + off];
        float f3 = FS[(size_t)sn3 * 192 + off];
        float v, t0, t1, t2, t3;
        v = f0 + fd; v = (v > 0.f) ? v : SLOPE * v; t0 = v * at;
        v = f1 + fd; v = (v > 0.f) ? v : SLOPE * v; t1 = v * at;
        v = f2 + fd; v = (v > 0.f) ? v : SLOPE * v; t2 = v * at;
        v = f3 + fd; v = (v > 0.f) ? v : SLOPE * v; t3 = v * at;

        float e0, e1, e2, e3;
        multi_reduce_exp4(t0, t1, t2, t3, e0, e1, e2, e3);

        den += (e0 + e1) + (e2 + e3);
        s += f0 * e0 + f1 * e1 + f2 * e2 + f3 * e3;
    }
    for (; p < pEnd; p++) {
        int sn = col[p];
        float f = FS[(size_t)sn * 192 + off];
        float v = f + fd; v = (v > 0.f) ? v : SLOPE * v;
        float t = v * at;
        #pragma unroll
        for (int o = 16; o > 0; o >>= 1) t += __shfl_xor_sync(0xffffffffu, t, o);
        float ex = __expf(t);
        den += ex; s += f * ex;
    }

    const float inv = (den > 0.f) ? (1.f / den) : 0.f;
    sm[off] = s * inv;
    __syncthreads();

    if (w == 0) {
        float m = 0.f;
        #pragma unroll
        for (int h = 0; h < 6; h++) m += sm[h * 32 + lane];
        out[(size_t)node * 32 + lane] = m * (1.f / 6.f) + resm[(size_t)node * 64 + lane];
    }
}

// ===========================================================================
// Host driver
// ===========================================================================
extern "C" void kernel_launch(void* const* d_in, const int* in_sizes, int n_in,
                              void* d_out, int out_size)
{
    const float* x   = (const float*)d_in[0];
    const int*   src = (const int*)d_in[1];
    const int*   dst = (const int*)d_in[2];
    const float* W0s = (const float*)d_in[3];
    const float* b0s = (const float*)d_in[4];
    const float* W0d = (const float*)d_in[5];
    const float* b0d = (const float*)d_in[6];
    const float* a0  = (const float*)d_in[7];
    const float* W1s = (const float*)d_in[8];
    const float* b1s = (const float*)d_in[9];
    const float* W1d = (const float*)d_in[10];
    const float* b1d = (const float*)d_in[11];
    const float* a1  = (const float*)d_in[12];
    const float* W2s = (const float*)d_in[13];
    const float* b2s = (const float*)d_in[14];
    const float* W2d = (const float*)d_in[15];
    const float* b2d = (const float*)d_in[16];
    const float* a2  = (const float*)d_in[17];
    const float* Wr2 = (const float*)d_in[18];
    const float* br2 = (const float*)d_in[19];

    const int N = in_sizes[0] / 128;
    const int E = in_sizes[1];

    float *FS, *FD, *HA, *BR2M;
    __nv_bfloat16 *AH, *AL, *WH, *WL;
    int *CNT, *ROWPTR, *CURS, *COL, *BLKSUM;
    cudaGetSymbolAddress((void**)&FS, g_FS);
    cudaGetSymbolAddress((void**)&FD, g_FD);
    cudaGetSymbolAddress((void**)&HA, g_HA);
    cudaGetSymbolAddress((void**)&BR2M, g_BR2M);
    cudaGetSymbolAddress((void**)&AH, g_AH);
    cudaGetSymbolAddress((void**)&AL, g_AL);
    cudaGetSymbolAddress((void**)&WH, g_WH);
    cudaGetSymbolAddress((void**)&WL, g_WL);
    cudaGetSymbolAddress((void**)&CNT, g_CNT);
    cudaGetSymbolAddress((void**)&ROWPTR, g_ROWPTR);
    cudaGetSymbolAddress((void**)&CURS, g_CURS);
    cudaGetSymbolAddress((void**)&COL, g_COL);
    cudaGetSymbolAddress((void**)&BLKSUM, g_BLKSUM);

    float* out = (float*)d_out;

    const int TB = 256;
    const int mTiles = cdiv(N, 128);

    // order: prep(1) scan_blk(2) scan_fix(3) gemm0(4=profiled) fill(5) agg0(6)...
    {
        PrepP pp;
        pp.x = x;
        pp.W[0] = W0s; pp.W[1] = W0d; pp.W[2] = W1s; pp.W[3] = W1d;
        pp.W[4] = W2s; pp.W[5] = W2d; pp.Wr2 = Wr2; pp.br2 = br2;
        pp.dst = dst;
        pp.AH = AH; pp.AL = AL; pp.WH = WH; pp.WL = WL;
        pp.bm = BR2M; pp.cnt = CNT;
        pp.NX = N * 128; pp.E = E;
        const int total = pp.NX + WT_TOTAL + E;
        prep_kernel<<<cdiv(total, TB), TB>>>(pp);
    }
    scan_blk_kernel<<<SCAN_G, SCAN_B>>>(CNT, ROWPTR, BLKSUM, N);
    scan_fix_kernel<<<SCAN_G, SCAN_B>>>(BLKSUM, ROWPTR, CURS, N);

    // ---------------- Layer 0 GEMM: K=128 -> FS, FD ----------------
    {
        MmaP P;
        for (int i = 0; i < 8; i++) { P.selMap[i] = i >> 2; P.colMap[i] = (i & 3) * 64; }
        P.woff[0] = 0;     P.bias[0] = b0s; P.C[0] = FS; P.Cld[0] = 256;
        P.woff[1] = 32768; P.bias[1] = b0d; P.C[1] = FD; P.Cld[1] = 256;
        P.woff[2] = 0;     P.bias[2] = b0s; P.C[2] = FS; P.Cld[2] = 256;
        dim3 grid(mTiles, 8);
        gemm_mma_kernel<<<grid, 256>>>(AH, AL, WH, WL, P, N, 128);
    }

    fill_kernel<<<cdiv(E, TB), TB>>>(src, dst, CURS, COL, E);

    gat_agg_h4d64_kernel<0, 1><<<N, 128>>>(ROWPTR, COL, FS, FD, a0, nullptr, HA, AH, AL);

    // ---------------- Layer 1: K=256 -> FS, FD ----------------
    {
        MmaP P;
        for (int i = 0; i < 8; i++) { P.selMap[i] = i >> 2; P.colMap[i] = (i & 3) * 64; }
        P.woff[0] = 65536;  P.bias[0] = b1s; P.C[0] = FS; P.Cld[0] = 256;
        P.woff[1] = 131072; P.bias[1] = b1d; P.C[1] = FD; P.Cld[1] = 256;
        P.woff[2] = 0;      P.bias[2] = b1s; P.C[2] = FS; P.Cld[2] = 256;
        dim3 grid(mTiles, 8);
        gemm_mma_kernel<<<grid, 256>>>(AH, AL, WH, WL, P, N, 256);
    }
    gat_agg_h4d64_kernel<1, 0><<<N, 128>>>(ROWPTR, COL, FS, FD, a1, HA, nullptr, AH, AL);

    // ---------------- Layer 2: K=256 -> FS, FD (192) + resm (64) ------
    {
        MmaP P;
        const int sm_[7] = {0, 0, 0, 1, 1, 1, 2};
        const int cm_[7] = {0, 64, 128, 0, 64, 128, 0};
        for (int i = 0; i < 7; i++) { P.selMap[i] = sm_[i]; P.colMap[i] = cm_[i]; }
        P.selMap[7] = 0; P.colMap[7] = 0;
        P.woff[0] = 196608; P.bias[0] = b2s;  P.C[0] = FS; P.Cld[0] = 192;
        P.woff[1] = 245760; P.bias[1] = b2d;  P.C[1] = FD; P.Cld[1] = 192;
        P.woff[2] = 294912; P.bias[2] = BR2M; P.C[2] = HA; P.Cld[2] = 64;
        dim3 grid(mTiles, 7);
        gemm_mma_kernel<<<grid, 256>>>(AH, AL, WH, WL, P, N, 256);
    }
    gat_agg_l2_kernel<<<N, 192>>>(ROWPTR, COL, FS, FD, a2, HA, out);
}